// round 10
// baseline (speedup 1.0000x reference)
#include <cuda_runtime.h>
#include <cuda_bf16.h>
#include <math.h>
#include <stdint.h>

#define B_TOK   4096
#define DM      1024
#define DH      2048
#define N_TILES 8

typedef __nv_bfloat16 bf16;

// ---------------- scratch (device globals; no allocation allowed) -----------
__device__ bf16  g_xhi [B_TOK * DM];
__device__ bf16  g_xlo [B_TOK * DM];
__device__ float g_Hr  [B_TOK * DM];
__device__ bf16  g_H2hi[B_TOK * DH];
__device__ bf16  g_H2lo[B_TOK * DH];
__device__ bf16  g_selhi[B_TOK * DM];
__device__ bf16  g_sello[B_TOK * DM];
__device__ int   g_tile[B_TOK];
__device__ int   g_perm[B_TOK];
__device__ int   g_cnt[N_TILES];
__device__ int   g_off[N_TILES];
__device__ int   g_cur[N_TILES];

// ---------------- helpers ----------------------------------------------------
__device__ __forceinline__ uint32_t smem_u32(const void* p) {
    uint32_t a;
    asm("{ .reg .u64 t; cvta.to.shared.u64 t, %1; cvt.u32.u64 %0, t; }"
        : "=r"(a) : "l"(p));
    return a;
}
__device__ __forceinline__ void cp_async16(uint32_t dst, const void* src) {
    asm volatile("cp.async.cg.shared.global [%0], [%1], 16;"
                 :: "r"(dst), "l"(src) : "memory");
}
__device__ __forceinline__ void cp_commit() {
    asm volatile("cp.async.commit_group;" ::: "memory");
}
__device__ __forceinline__ void cp_wait1() {
    asm volatile("cp.async.wait_group 1;" ::: "memory");
}
__device__ __forceinline__ void ldsm_x4(uint32_t* r, uint32_t addr) {
    asm volatile("ldmatrix.sync.aligned.m8n8.x4.shared.b16 {%0,%1,%2,%3}, [%4];"
                 : "=r"(r[0]), "=r"(r[1]), "=r"(r[2]), "=r"(r[3]) : "r"(addr));
}
__device__ __forceinline__ void ldsm_x4_t(uint32_t* r, uint32_t addr) {
    asm volatile("ldmatrix.sync.aligned.m8n8.x4.trans.shared.b16 {%0,%1,%2,%3}, [%4];"
                 : "=r"(r[0]), "=r"(r[1]), "=r"(r[2]), "=r"(r[3]) : "r"(addr));
}
__device__ __forceinline__ void mma16816(float* c, const uint32_t* a, const uint32_t* b) {
    asm volatile("mma.sync.aligned.m16n8k16.row.col.f32.bf16.bf16.f32 "
                 "{%0,%1,%2,%3}, {%4,%5,%6,%7}, {%8,%9}, {%0,%1,%2,%3};"
                 : "+f"(c[0]), "+f"(c[1]), "+f"(c[2]), "+f"(c[3])
                 : "r"(a[0]), "r"(a[1]), "r"(a[2]), "r"(a[3]),
                   "r"(b[0]), "r"(b[1]));
}
__device__ __forceinline__ float gelu_exact(float v) {
    return 0.5f * v * (1.0f + erff(v * 0.70710678118654752440f));
}
__device__ __forceinline__ uint32_t pack_hi2(float a, float b) {
    __nv_bfloat162 p(__float2bfloat16(a), __float2bfloat16(b));
    return *(uint32_t*)&p;
}
__device__ __forceinline__ uint32_t pack_lo2(float a, float b, uint32_t hi) {
    __nv_bfloat162 h = *(__nv_bfloat162*)&hi;
    __nv_bfloat162 p(__float2bfloat16(a - __bfloat162float(h.x)),
                     __float2bfloat16(b - __bfloat162float(h.y)));
    return *(uint32_t*)&p;
}

// ---------------- small kernels ---------------------------------------------
__global__ void zero_kernel() {
    int i = threadIdx.x;
    if (i < N_TILES) { g_cnt[i] = 0; g_cur[i] = 0; }
}

__global__ void split_acts_kernel(const float* __restrict__ src,
                                  bf16* __restrict__ xhi, bf16* __restrict__ xlo) {
    int i = blockIdx.x * blockDim.x + threadIdx.x;   // float4 index
    const float4 v = ((const float4*)src)[i];
    uint32_t h0 = pack_hi2(v.x, v.y), h1 = pack_hi2(v.z, v.w);
    uint32_t l0 = pack_lo2(v.x, v.y, h0), l1 = pack_lo2(v.z, v.w, h1);
    ((uint2*)xhi)[i] = make_uint2(h0, h1);
    ((uint2*)xlo)[i] = make_uint2(l0, l1);
}

// ---------------- router logits + argmax ------------------------------------
__global__ __launch_bounds__(256) void router_argmax_kernel(
    const float* __restrict__ Hr, const float* __restrict__ Wr2,
    const float* __restrict__ br2,
    float* __restrict__ out_logits, float* __restrict__ out_idx)
{
    const int token = blockIdx.x * 8 + (threadIdx.x >> 5);
    const int lane  = threadIdx.x & 31;
    const float* h  = Hr + (size_t)token * DM;

    float acc[N_TILES];
#pragma unroll
    for (int n = 0; n < N_TILES; n++) acc[n] = 0.f;
    for (int k = lane; k < DM; k += 32) {
        float hv = h[k];
        float4 w0 = *(const float4*)(Wr2 + (size_t)k * N_TILES);
        float4 w1 = *(const float4*)(Wr2 + (size_t)k * N_TILES + 4);
        acc[0] = fmaf(hv, w0.x, acc[0]); acc[1] = fmaf(hv, w0.y, acc[1]);
        acc[2] = fmaf(hv, w0.z, acc[2]); acc[3] = fmaf(hv, w0.w, acc[3]);
        acc[4] = fmaf(hv, w1.x, acc[4]); acc[5] = fmaf(hv, w1.y, acc[5]);
        acc[6] = fmaf(hv, w1.z, acc[6]); acc[7] = fmaf(hv, w1.w, acc[7]);
    }
#pragma unroll
    for (int n = 0; n < N_TILES; n++)
#pragma unroll
        for (int s = 16; s > 0; s >>= 1)
            acc[n] += __shfl_xor_sync(0xFFFFFFFFu, acc[n], s);
    if (lane == 0) {
        float best = -1e30f; int bi = 0;
#pragma unroll
        for (int n = 0; n < N_TILES; n++) {
            float l = (acc[n] + br2[n]) * 2.0f;
            if (out_logits) out_logits[(size_t)token * N_TILES + n] = l;
            if (l > best) { best = l; bi = n; }
        }
        g_tile[token] = bi;
        atomicAdd(&g_cnt[bi], 1);
        if (out_idx) out_idx[token] = (float)bi;
    }
}

__global__ void offsets_kernel() {
    if (threadIdx.x == 0) {
        int s = 0;
        for (int t = 0; t < N_TILES; t++) { g_off[t] = s; s += g_cnt[t]; }
    }
}

__global__ void scatter_kernel() {
    int i = blockIdx.x * blockDim.x + threadIdx.x;
    if (i < B_TOK) {
        int t = g_tile[i];
        int pos = g_off[t] + atomicAdd(&g_cur[t], 1);
        g_perm[pos] = i;
    }
}

// ---------------- HMMA bf16x3 GEMM, fragment double-buffered -----------------
// C[M,N] = act(A[M,K] @ W[K,N] + b).
// A: hi/lo bf16 row-major via 3-stage cp.async.  W: fp32 [K][N] direct;
// loader converts to hi/lo bf16 in-register, STS K-major, B fragments via
// ldmatrix.x4.trans.  bf16x3: hi*hi + hi*lo + lo*hi, fp32 accumulation.
// Block 128x128, 256 threads, 8 warps (2Mx4N), warp tile 64x32, BK=16,
// 3 stages x 16KB = 48KB static smem.
// NEW: fragments for stage kt+1 are LDSM'd at iter kt, before the 48-MMA
// block on f(kt) — LDSM latency drains in the MIO queue under the MMAs.

#define BK       16
#define AROWB    32                     // A row bytes (BK bf16)
#define BROWB    256                    // B row bytes (128 bf16)
#define SOFF_AHI 0
#define SOFF_ALO 4096
#define SOFF_BHI 8192
#define SOFF_BLO 12288
#define STAGE_B  16384
#define NSTAGE   3

struct Frags {
    uint32_t Ah[4][4];
    uint32_t Al[4][4];
    uint32_t Bh[8];
    uint32_t Bl[8];
};

template<int MODE, bool ACT, bool F32OUT>
__global__ void __launch_bounds__(256) hgemm_kernel(
    const bf16* __restrict__ Ahi, const bf16* __restrict__ Alo,
    const float* __restrict__ Wf,
    const float* __restrict__ bg,
    float* __restrict__ Cf, bf16* __restrict__ Chi, bf16* __restrict__ Clo,
    int N, int K, int M0)
{
    const int tile = (MODE == 0) ? 0 : blockIdx.z;
    int Mvalid, moff;
    if (MODE == 0) { Mvalid = M0;          moff = 0; }
    else           { Mvalid = g_cnt[tile]; moff = g_off[tile]; }

    const int mstart = blockIdx.y * 128;
    if (mstart >= Mvalid) return;
    const int nstart = blockIdx.x * 128;

    __shared__ __align__(128) char smem[NSTAGE * STAGE_B];
    const uint32_t sb = smem_u32(smem);
    const int tid  = threadIdx.x;
    const int wid  = tid >> 5;
    const int lane = tid & 31;
    const int warp_m = (wid & 1) * 64;
    const int warp_n = (wid >> 1) * 32;
    const int g     = lane >> 2;
    const int tig   = lane & 3;
    const int matid = lane >> 3;
    const int mrow8 = lane & 7;

    // ---- A loader (cp.async) ----
    const int lrow = tid >> 1;
    const int kc   = tid & 1;
    const int keo  = kc * 8;
    int mg = mstart + lrow; if (mg > Mvalid - 1) mg = Mvalid - 1;
    size_t aidx;
    if (MODE == 0)      aidx = (size_t)mg;
    else if (MODE == 1) aidx = (size_t)g_perm[moff + mg];
    else                aidx = (size_t)(moff + mg);
    const bf16* gah = Ahi + aidx * (size_t)K;
    const bf16* gal = Alo + aidx * (size_t)K;
    const uint32_t astoff = (uint32_t)lrow * AROWB + (uint32_t)kc * 16;

    // ---- B loader (LDG fp32 + cvt + STS) ----
    const int brow = tid >> 4;
    const int bseg = tid & 15;
    const float* gbf = Wf + (size_t)tile * (size_t)K * (size_t)N
                          + (size_t)nstart + (size_t)bseg * 8;
    const uint32_t bstoff = (uint32_t)brow * BROWB
                          + (uint32_t)(((bseg >> 1) ^ (brow & 7)) * 32)
                          + (uint32_t)((bseg & 1) * 16);

    // ---- ldmatrix addresses ----
    const uint32_t a_ls = (uint32_t)(warp_m + (matid & 1) * 8 + mrow8) * AROWB
                        + (uint32_t)(matid >> 1) * 16;
    const uint32_t bt_row = (uint32_t)((matid & 1) * 8 + mrow8) * BROWB
                          + (uint32_t)(matid >> 1) * 16;
    const uint32_t bt_c0 = (uint32_t)((((warp_n >> 4) + 0) ^ mrow8) * 32);
    const uint32_t bt_c1 = (uint32_t)((((warp_n >> 4) + 1) ^ mrow8) * 32);

    const int nk = K / BK;

    float4 bf0, bf1;   // fp32 B register stage

    // STS helper (captures bstoff)
    auto stsB = [&](char* buf) {
        uint32_t h0 = pack_hi2(bf0.x, bf0.y), h1 = pack_hi2(bf0.z, bf0.w);
        uint32_t h2 = pack_hi2(bf1.x, bf1.y), h3 = pack_hi2(bf1.z, bf1.w);
        uint32_t l0 = pack_lo2(bf0.x, bf0.y, h0), l1 = pack_lo2(bf0.z, bf0.w, h1);
        uint32_t l2 = pack_lo2(bf1.x, bf1.y, h2), l3 = pack_lo2(bf1.z, bf1.w, h3);
        *(uint4*)(buf + SOFF_BHI + bstoff) = make_uint4(h0, h1, h2, h3);
        *(uint4*)(buf + SOFF_BLO + bstoff) = make_uint4(l0, l1, l2, l3);
    };
    auto ldgB = [&](int kt) {
        const float* q = gbf + (size_t)(kt * BK + brow) * N;
        bf0 = *(const float4*)(q);
        bf1 = *(const float4*)(q + 4);
    };
    auto load_frags = [&](Frags& f, uint32_t st) {
        ldsm_x4_t(&f.Bh[0], st + SOFF_BHI + bt_row + bt_c0);
        ldsm_x4_t(&f.Bh[4], st + SOFF_BHI + bt_row + bt_c1);
        ldsm_x4_t(&f.Bl[0], st + SOFF_BLO + bt_row + bt_c0);
        ldsm_x4_t(&f.Bl[4], st + SOFF_BLO + bt_row + bt_c1);
#pragma unroll
        for (int mt = 0; mt < 4; mt++) {
            const uint32_t aa = st + a_ls + (uint32_t)mt * 16 * AROWB;
            ldsm_x4(f.Ah[mt], aa + SOFF_AHI);
            ldsm_x4(f.Al[mt], aa + SOFF_ALO);
        }
    };

    float acc[4][4][4];
#pragma unroll
    for (int i = 0; i < 4; i++)
#pragma unroll
        for (int j = 0; j < 4; j++)
#pragma unroll
            for (int c = 0; c < 4; c++) acc[i][j][c] = 0.f;

    // ---- prologue: A stages 0,1; B stages 0,1 + B(2) regs; f(0) fragments ----
    cp_async16(sb + 0 * STAGE_B + SOFF_AHI + astoff, gah + 0 * BK + keo);
    cp_async16(sb + 0 * STAGE_B + SOFF_ALO + astoff, gal + 0 * BK + keo);
    cp_commit();
    cp_async16(sb + 1 * STAGE_B + SOFF_AHI + astoff, gah + 1 * BK + keo);
    cp_async16(sb + 1 * STAGE_B + SOFF_ALO + astoff, gal + 1 * BK + keo);
    cp_commit();
    ldgB(0); stsB(smem + 0 * STAGE_B);
    ldgB(1); stsB(smem + 1 * STAGE_B);
    ldgB(2);
    cp_wait1();            // A(0) complete
    __syncthreads();

    Frags f0, f1;
    load_frags(f0, sb + 0 * STAGE_B);

    auto mma_all = [&](const Frags& f) {
#pragma unroll
        for (int mt = 0; mt < 4; mt++) {
#pragma unroll
            for (int nt = 0; nt < 4; nt++) {
                const uint32_t* bh = &f.Bh[(nt >> 1) * 4 + (nt & 1) * 2];
                const uint32_t* bl = &f.Bl[(nt >> 1) * 4 + (nt & 1) * 2];
                mma16816(acc[mt][nt], f.Ah[mt], bh);
                mma16816(acc[mt][nt], f.Ah[mt], bl);
                mma16816(acc[mt][nt], f.Al[mt], bh);
            }
        }
    };

    // stage counters: s1 = (kt+1)%3, s2 = (kt+2)%3
    int s1 = 1, s2 = 2;
    auto iter_body = [&](Frags& cur, Frags& nxt, int kt) {
        // A(kt+2) into stage s2 (readers finished >=2 barriers ago)
        if (kt + 2 < nk) {
            const uint32_t buf = sb + s2 * STAGE_B;
            const int k0 = (kt + 2) * BK;
            cp_async16(buf + SOFF_AHI + astoff, gah + k0 + keo);
            cp_async16(buf + SOFF_ALO + astoff, gal + k0 + keo);
        }
        cp_commit();
        cp_wait1();            // A(kt+1) complete
        __syncthreads();       // B(kt+1) STS visible; stage s2 write-safe

        // prefetch next fragments + B pipeline — all independent of MMAs below
        if (kt + 1 < nk) load_frags(nxt, sb + s1 * STAGE_B);
        if (kt + 2 < nk) stsB(smem + s2 * STAGE_B);   // B(kt+2) from regs
        if (kt + 3 < nk) ldgB(kt + 3);                // B(kt+3) -> regs

        mma_all(cur);

        s1 = (s1 == NSTAGE - 1) ? 0 : s1 + 1;
        s2 = (s2 == NSTAGE - 1) ? 0 : s2 + 1;
    };

    // nk is even (K = 1024 or 2048 -> nk = 64 or 128)
    for (int kt = 0; kt < nk; kt += 2) {
        iter_body(f0, f1, kt);
        iter_body(f1, f0, kt + 1);
    }

    // ---- epilogue ----
    const float* bias = bg + (size_t)tile * N;
#pragma unroll
    for (int mt = 0; mt < 4; mt++) {
#pragma unroll
        for (int half = 0; half < 2; half++) {
            const int m = mstart + warp_m + mt * 16 + g + half * 8;
            if (m >= Mvalid) continue;
            size_t orow;
            if (MODE == 0)      orow = (size_t)m;
            else if (MODE == 1) orow = (size_t)(moff + m);
            else                orow = (size_t)g_perm[moff + m];
#pragma unroll
            for (int nt = 0; nt < 4; nt++) {
                const int n = nstart + warp_n + nt * 8 + tig * 2;
                float v0 = acc[mt][nt][half * 2 + 0] + bias[n + 0];
                float v1 = acc[mt][nt][half * 2 + 1] + bias[n + 1];
                if (ACT) { v0 = gelu_exact(v0); v1 = gelu_exact(v1); }
                if (F32OUT) {
                    *(float2*)(Cf + orow * (size_t)N + n) = make_float2(v0, v1);
                } else {
                    uint32_t h = pack_hi2(v0, v1);
                    uint32_t l = pack_lo2(v0, v1, h);
                    *(uint32_t*)(Chi + orow * (size_t)N + n) = h;
                    *(uint32_t*)(Clo + orow * (size_t)N + n) = l;
                }
            }
        }
    }
}

// ---------------- launch -----------------------------------------------------
// __device__ globals passed as kernel args MUST be resolved through
// cudaGetSymbolAddress (host shadow vs device copy under ATS on GB300).
#define SYMADDR(T, var, sym) \
    T* var; { void* _p; cudaGetSymbolAddress(&_p, sym); var = (T*)_p; }

extern "C" void kernel_launch(void* const* d_in, const int* in_sizes, int n_in,
                              void* d_out, int out_size)
{
    const float* x   = (const float*)d_in[0];
    const float* Wr1 = (const float*)d_in[1];
    const float* br1 = (const float*)d_in[2];
    const float* Wr2 = (const float*)d_in[3];
    const float* br2 = (const float*)d_in[4];
    const float* W1  = (const float*)d_in[5];
    const float* b1  = (const float*)d_in[6];
    const float* W2  = (const float*)d_in[7];
    const float* b2  = (const float*)d_in[8];
    const float* Wo  = (const float*)d_in[9];
    const float* bo  = (const float*)d_in[10];

    SYMADDR(bf16,  xhi,   g_xhi);   SYMADDR(bf16,  xlo,   g_xlo);
    SYMADDR(float, Hr,    g_Hr);
    SYMADDR(bf16,  H2hi,  g_H2hi);  SYMADDR(bf16,  H2lo,  g_H2lo);
    SYMADDR(bf16,  selhi, g_selhi); SYMADDR(bf16,  sello, g_sello);

    float* out = (float*)d_out;
    float* out_main   = out;
    float* out_idx    = nullptr;
    float* out_logits = nullptr;
    const long long need_all = (long long)B_TOK * DM + B_TOK + (long long)B_TOK * N_TILES;
    if ((long long)out_size >= need_all) {
        out_idx    = out + (size_t)B_TOK * DM;
        out_logits = out + (size_t)B_TOK * DM + B_TOK;
    } else if ((long long)out_size >= (long long)B_TOK * DM + B_TOK) {
        out_idx = out + (size_t)B_TOK * DM;
    }

    // 1) counters + activation split
    zero_kernel<<<1, 32>>>();
    split_acts_kernel<<<(B_TOK * DM / 4) / 256, 256>>>(x, xhi, xlo);

    // 2) router hidden: Hr = gelu(x @ Wr1 + br1)  (fp32 out)
    hgemm_kernel<0, true, true><<<dim3(DM / 128, B_TOK / 128), 256>>>(
        xhi, xlo, Wr1, br1, Hr, nullptr, nullptr, DM, DM, B_TOK);

    // 3) logits + argmax + counts; 4) offsets + scatter
    router_argmax_kernel<<<B_TOK / 8, 256>>>(Hr, Wr2, br2, out_logits, out_idx);
    offsets_kernel<<<1, 1>>>();
    scatter_kernel<<<B_TOK / 256, 256>>>();

    // 5) tile MLP layer 1: gather x rows, gelu, hi/lo out (compact order)
    hgemm_kernel<1, true, false><<<dim3(DH / 128, B_TOK / 128, N_TILES), 256>>>(
        xhi, xlo, W1, b1, nullptr, H2hi, H2lo, DH, DM, 0);

    // 6) tile MLP layer 2: compact in, scatter out, hi/lo
    hgemm_kernel<2, false, false><<<dim3(DM / 128, B_TOK / 128, N_TILES), 256>>>(
        H2hi, H2lo, W2, b2, nullptr, selhi, sello, DM, DH, 0);

    // 7) output projection (fp32 out to d_out)
    hgemm_kernel<0, false, true><<<dim3(DM / 128, B_TOK / 128), 256>>>(
        selhi, sello, Wo, bo, out_main, nullptr, nullptr, DM, DM, B_TOK);
}

// round 11
// speedup vs baseline: 1.7395x; 1.7395x over previous
#include <cuda_runtime.h>
#include <cuda_fp16.h>
#include <math.h>
#include <stdint.h>

#define B_TOK   4096
#define DM      1024
#define DH      2048
#define N_TILES 8

typedef __half fp16;

// ---------------- scratch (device globals; no allocation allowed) -----------
__device__ fp16  g_xhi [B_TOK * DM];
__device__ fp16  g_xlo [B_TOK * DM];
__device__ float g_Hr  [B_TOK * DM];
__device__ fp16  g_H2  [B_TOK * DH];
__device__ fp16  g_sel [B_TOK * DM];
__device__ int   g_tile[B_TOK];
__device__ int   g_perm[B_TOK];
__device__ int   g_cnt[N_TILES];
__device__ int   g_off[N_TILES];
__device__ int   g_cur[N_TILES];

// ---------------- helpers ----------------------------------------------------
__device__ __forceinline__ uint32_t smem_u32(const void* p) {
    uint32_t a;
    asm("{ .reg .u64 t; cvta.to.shared.u64 t, %1; cvt.u32.u64 %0, t; }"
        : "=r"(a) : "l"(p));
    return a;
}
__device__ __forceinline__ void cp_async16(uint32_t dst, const void* src) {
    asm volatile("cp.async.cg.shared.global [%0], [%1], 16;"
                 :: "r"(dst), "l"(src) : "memory");
}
__device__ __forceinline__ void cp_commit() {
    asm volatile("cp.async.commit_group;" ::: "memory");
}
__device__ __forceinline__ void cp_wait1() {
    asm volatile("cp.async.wait_group 1;" ::: "memory");
}
__device__ __forceinline__ void ldsm_x4(uint32_t* r, uint32_t addr) {
    asm volatile("ldmatrix.sync.aligned.m8n8.x4.shared.b16 {%0,%1,%2,%3}, [%4];"
                 : "=r"(r[0]), "=r"(r[1]), "=r"(r[2]), "=r"(r[3]) : "r"(addr));
}
__device__ __forceinline__ void ldsm_x4_t(uint32_t* r, uint32_t addr) {
    asm volatile("ldmatrix.sync.aligned.m8n8.x4.trans.shared.b16 {%0,%1,%2,%3}, [%4];"
                 : "=r"(r[0]), "=r"(r[1]), "=r"(r[2]), "=r"(r[3]) : "r"(addr));
}
__device__ __forceinline__ void mma16816(float* c, const uint32_t* a, const uint32_t* b) {
    asm volatile("mma.sync.aligned.m16n8k16.row.col.f32.f16.f16.f32 "
                 "{%0,%1,%2,%3}, {%4,%5,%6,%7}, {%8,%9}, {%0,%1,%2,%3};"
                 : "+f"(c[0]), "+f"(c[1]), "+f"(c[2]), "+f"(c[3])
                 : "r"(a[0]), "r"(a[1]), "r"(a[2]), "r"(a[3]),
                   "r"(b[0]), "r"(b[1]));
}
__device__ __forceinline__ float gelu_exact(float v) {
    return 0.5f * v * (1.0f + erff(v * 0.70710678118654752440f));
}
__device__ __forceinline__ uint32_t pack_hi2(float a, float b) {
    __half2 p(__float2half_rn(a), __float2half_rn(b));
    return *(uint32_t*)&p;
}
__device__ __forceinline__ uint32_t pack_lo2(float a, float b, uint32_t hi) {
    __half2 h = *(__half2*)&hi;
    __half2 p(__float2half_rn(a - __half2float(h.x)),
              __float2half_rn(b - __half2float(h.y)));
    return *(uint32_t*)&p;
}

// ---------------- small kernels ---------------------------------------------
__global__ void zero_kernel() {
    int i = threadIdx.x;
    if (i < N_TILES) { g_cnt[i] = 0; g_cur[i] = 0; }
}

__global__ void split_acts_kernel(const float* __restrict__ src,
                                  fp16* __restrict__ xhi, fp16* __restrict__ xlo) {
    int i = blockIdx.x * blockDim.x + threadIdx.x;   // float4 index
    const float4 v = ((const float4*)src)[i];
    uint32_t h0 = pack_hi2(v.x, v.y), h1 = pack_hi2(v.z, v.w);
    uint32_t l0 = pack_lo2(v.x, v.y, h0), l1 = pack_lo2(v.z, v.w, h1);
    ((uint2*)xhi)[i] = make_uint2(h0, h1);
    ((uint2*)xlo)[i] = make_uint2(l0, l1);
}

// ---------------- router logits + argmax ------------------------------------
__global__ __launch_bounds__(256) void router_argmax_kernel(
    const float* __restrict__ Hr, const float* __restrict__ Wr2,
    const float* __restrict__ br2,
    float* __restrict__ out_logits, float* __restrict__ out_idx)
{
    const int token = blockIdx.x * 8 + (threadIdx.x >> 5);
    const int lane  = threadIdx.x & 31;
    const float* h  = Hr + (size_t)token * DM;

    float acc[N_TILES];
#pragma unroll
    for (int n = 0; n < N_TILES; n++) acc[n] = 0.f;
    for (int k = lane; k < DM; k += 32) {
        float hv = h[k];
        float4 w0 = *(const float4*)(Wr2 + (size_t)k * N_TILES);
        float4 w1 = *(const float4*)(Wr2 + (size_t)k * N_TILES + 4);
        acc[0] = fmaf(hv, w0.x, acc[0]); acc[1] = fmaf(hv, w0.y, acc[1]);
        acc[2] = fmaf(hv, w0.z, acc[2]); acc[3] = fmaf(hv, w0.w, acc[3]);
        acc[4] = fmaf(hv, w1.x, acc[4]); acc[5] = fmaf(hv, w1.y, acc[5]);
        acc[6] = fmaf(hv, w1.z, acc[6]); acc[7] = fmaf(hv, w1.w, acc[7]);
    }
#pragma unroll
    for (int n = 0; n < N_TILES; n++)
#pragma unroll
        for (int s = 16; s > 0; s >>= 1)
            acc[n] += __shfl_xor_sync(0xFFFFFFFFu, acc[n], s);
    if (lane == 0) {
        float best = -1e30f; int bi = 0;
#pragma unroll
        for (int n = 0; n < N_TILES; n++) {
            float l = (acc[n] + br2[n]) * 2.0f;
            if (out_logits) out_logits[(size_t)token * N_TILES + n] = l;
            if (l > best) { best = l; bi = n; }
        }
        g_tile[token] = bi;
        atomicAdd(&g_cnt[bi], 1);
        if (out_idx) out_idx[token] = (float)bi;
    }
}

__global__ void offsets_kernel() {
    if (threadIdx.x == 0) {
        int s = 0;
        for (int t = 0; t < N_TILES; t++) { g_off[t] = s; s += g_cnt[t]; }
    }
}

__global__ void scatter_kernel() {
    int i = blockIdx.x * blockDim.x + threadIdx.x;
    if (i < B_TOK) {
        int t = g_tile[i];
        int pos = g_off[t] + atomicAdd(&g_cur[t], 1);
        g_perm[pos] = i;
    }
}

// ---------------- HMMA fp16-split GEMM, fused fp32-weight conversion ---------
// C[M,N] = act(A[M,K] @ W[K,N] + b).
// W: fp32 [K][N] direct; loader converts to hi/lo fp16 in-register, STS
// K-major tiles, B fragments via ldmatrix.x4.trans.
// NTERM==3 (router): A = Ahi + Alo fp16; D = Ah*Bh + Ah*Bl + Al*Bh
//   (error ~2^-22 — protects the argmax).
// NTERM==2 (big GEMMs): A = Ahi only; D = Ah*Bh + Ah*Bl = Ah*W (exact in W;
//   omitted Alo*W ~2^-11 rel). A traffic halves, 32 MMA/iter instead of 48.
// Block 128x128, 256 threads, 8 warps (2Mx4N), warp tile 64x32, BK=16.
// 3 stages x 16KB = 48KB static smem (R8-proven loop structure).

#define BK       16
#define AROWB    32                     // A row bytes (BK fp16)
#define BROWB    256                    // B row bytes (128 fp16)
#define SOFF_AHI 0
#define SOFF_ALO 4096
#define SOFF_BHI 8192
#define SOFF_BLO 12288
#define STAGE_B  16384
#define NSTAGE   3

template<int MODE, int NTERM, bool ACT, bool F32OUT>
__global__ void __launch_bounds__(256) hgemm_kernel(
    const fp16* __restrict__ Ahi, const fp16* __restrict__ Alo,
    const float* __restrict__ Wf,
    const float* __restrict__ bg,
    float* __restrict__ Cf, fp16* __restrict__ Ch,
    int N, int K, int M0)
{
    const int tile = (MODE == 0) ? 0 : blockIdx.z;
    int Mvalid, moff;
    if (MODE == 0) { Mvalid = M0;          moff = 0; }
    else           { Mvalid = g_cnt[tile]; moff = g_off[tile]; }

    const int mstart = blockIdx.y * 128;
    if (mstart >= Mvalid) return;
    const int nstart = blockIdx.x * 128;

    __shared__ __align__(128) char smem[NSTAGE * STAGE_B];
    const uint32_t sb = smem_u32(smem);
    const int tid  = threadIdx.x;
    const int wid  = tid >> 5;
    const int lane = tid & 31;
    const int warp_m = (wid & 1) * 64;
    const int warp_n = (wid >> 1) * 32;
    const int g     = lane >> 2;
    const int tig   = lane & 3;
    const int matid = lane >> 3;
    const int mrow8 = lane & 7;

    // ---- A loader (cp.async): one row per thread-pair, 16B chunk tid&1 ----
    const int lrow = tid >> 1;
    const int kc   = tid & 1;
    const int keo  = kc * 8;
    int mg = mstart + lrow; if (mg > Mvalid - 1) mg = Mvalid - 1;
    size_t aidx;
    if (MODE == 0)      aidx = (size_t)mg;
    else if (MODE == 1) aidx = (size_t)g_perm[moff + mg];
    else                aidx = (size_t)(moff + mg);
    const fp16* gah = Ahi + aidx * (size_t)K;
    const fp16* gal = (NTERM == 3) ? (Alo + aidx * (size_t)K) : nullptr;
    const uint32_t astoff = (uint32_t)lrow * AROWB + (uint32_t)kc * 16;

    // ---- B loader (LDG fp32 + cvt + STS): row tid>>4, 8-float seg tid&15 ----
    const int brow = tid >> 4;
    const int bseg = tid & 15;
    const float* gbf = Wf + (size_t)tile * (size_t)K * (size_t)N
                          + (size_t)nstart + (size_t)bseg * 8;
    const uint32_t bstoff = (uint32_t)brow * BROWB
                          + (uint32_t)(((bseg >> 1) ^ (brow & 7)) * 32)
                          + (uint32_t)((bseg & 1) * 16);

    // ---- ldmatrix addresses ----
    const uint32_t a_ls = (uint32_t)(warp_m + (matid & 1) * 8 + mrow8) * AROWB
                        + (uint32_t)(matid >> 1) * 16;
    const uint32_t bt_row = (uint32_t)((matid & 1) * 8 + mrow8) * BROWB
                          + (uint32_t)(matid >> 1) * 16;
    const uint32_t bt_c0 = (uint32_t)((((warp_n >> 4) + 0) ^ mrow8) * 32);
    const uint32_t bt_c1 = (uint32_t)((((warp_n >> 4) + 1) ^ mrow8) * 32);

    const int nk = K / BK;

    float4 bf0, bf1;   // fp32 B register stage

    // ---- prologue ----
#pragma unroll
    for (int s = 0; s < 2; s++) {
        const uint32_t buf = sb + s * STAGE_B;
        cp_async16(buf + SOFF_AHI + astoff, gah + s * BK + keo);
        if (NTERM == 3)
            cp_async16(buf + SOFF_ALO + astoff, gal + s * BK + keo);
        cp_commit();
    }
    {
        const float* p = gbf + (size_t)brow * N;
        bf0 = *(const float4*)(p);
        bf1 = *(const float4*)(p + 4);
        uint32_t h0 = pack_hi2(bf0.x, bf0.y), h1 = pack_hi2(bf0.z, bf0.w);
        uint32_t h2 = pack_hi2(bf1.x, bf1.y), h3 = pack_hi2(bf1.z, bf1.w);
        uint32_t l0 = pack_lo2(bf0.x, bf0.y, h0), l1 = pack_lo2(bf0.z, bf0.w, h1);
        uint32_t l2 = pack_lo2(bf1.x, bf1.y, h2), l3 = pack_lo2(bf1.z, bf1.w, h3);
        *(uint4*)(smem + SOFF_BHI + bstoff) = make_uint4(h0, h1, h2, h3);
        *(uint4*)(smem + SOFF_BLO + bstoff) = make_uint4(l0, l1, l2, l3);
        if (nk > 1) {
            const float* q = gbf + (size_t)(BK + brow) * N;
            bf0 = *(const float4*)(q);
            bf1 = *(const float4*)(q + 4);
        }
    }

    float acc[4][4][4];
#pragma unroll
    for (int i = 0; i < 4; i++)
#pragma unroll
        for (int j = 0; j < 4; j++)
#pragma unroll
            for (int c = 0; c < 4; c++) acc[i][j][c] = 0.f;

    int sc = 0;   // stage of kt
    int sp = 2;   // stage of kt+2
    for (int kt = 0; kt < nk; kt++) {
        cp_wait1();
        __syncthreads();

        // A(kt+2) via cp.async into stage sp
        if (kt + 2 < nk) {
            const uint32_t buf = sb + sp * STAGE_B;
            const int k0 = (kt + 2) * BK;
            cp_async16(buf + SOFF_AHI + astoff, gah + k0 + keo);
            if (NTERM == 3)
                cp_async16(buf + SOFF_ALO + astoff, gal + k0 + keo);
        }
        cp_commit();

        // B(kt+1): convert regs -> STS into stage (kt+1)%3
        if (kt + 1 < nk) {
            char* buf = smem + ((sc + 1) % NSTAGE) * STAGE_B;
            uint32_t h0 = pack_hi2(bf0.x, bf0.y), h1 = pack_hi2(bf0.z, bf0.w);
            uint32_t h2 = pack_hi2(bf1.x, bf1.y), h3 = pack_hi2(bf1.z, bf1.w);
            uint32_t l0 = pack_lo2(bf0.x, bf0.y, h0), l1 = pack_lo2(bf0.z, bf0.w, h1);
            uint32_t l2 = pack_lo2(bf1.x, bf1.y, h2), l3 = pack_lo2(bf1.z, bf1.w, h3);
            *(uint4*)(buf + SOFF_BHI + bstoff) = make_uint4(h0, h1, h2, h3);
            *(uint4*)(buf + SOFF_BLO + bstoff) = make_uint4(l0, l1, l2, l3);
        }
        // B(kt+2) -> regs
        if (kt + 2 < nk) {
            const float* q = gbf + (size_t)((kt + 2) * BK + brow) * N;
            bf0 = *(const float4*)(q);
            bf1 = *(const float4*)(q + 4);
        }

        const uint32_t st = sb + sc * STAGE_B;

        // B fragments via ldmatrix.trans
        uint32_t Bh[8], Bl[8];
        ldsm_x4_t(&Bh[0], st + SOFF_BHI + bt_row + bt_c0);
        ldsm_x4_t(&Bh[4], st + SOFF_BHI + bt_row + bt_c1);
        ldsm_x4_t(&Bl[0], st + SOFF_BLO + bt_row + bt_c0);
        ldsm_x4_t(&Bl[4], st + SOFF_BLO + bt_row + bt_c1);

#pragma unroll
        for (int mt = 0; mt < 4; mt++) {
            const uint32_t aa = st + a_ls + (uint32_t)mt * 16 * AROWB;
            uint32_t Ah[4], Al[4];
            ldsm_x4(Ah, aa + SOFF_AHI);
            if (NTERM == 3) ldsm_x4(Al, aa + SOFF_ALO);
#pragma unroll
            for (int nt = 0; nt < 4; nt++) {
                const uint32_t* bh = &Bh[(nt >> 1) * 4 + (nt & 1) * 2];
                const uint32_t* bl = &Bl[(nt >> 1) * 4 + (nt & 1) * 2];
                mma16816(acc[mt][nt], Ah, bh);
                mma16816(acc[mt][nt], Ah, bl);
                if (NTERM == 3) mma16816(acc[mt][nt], Al, bh);
            }
        }

        sc = (sc == NSTAGE - 1) ? 0 : sc + 1;
        sp = (sp == NSTAGE - 1) ? 0 : sp + 1;
    }

    // ---- epilogue ----
    const float* bias = bg + (size_t)tile * N;
#pragma unroll
    for (int mt = 0; mt < 4; mt++) {
#pragma unroll
        for (int half = 0; half < 2; half++) {
            const int m = mstart + warp_m + mt * 16 + g + half * 8;
            if (m >= Mvalid) continue;
            size_t orow;
            if (MODE == 0)      orow = (size_t)m;
            else if (MODE == 1) orow = (size_t)(moff + m);
            else                orow = (size_t)g_perm[moff + m];
#pragma unroll
            for (int nt = 0; nt < 4; nt++) {
                const int n = nstart + warp_n + nt * 8 + tig * 2;
                float v0 = acc[mt][nt][half * 2 + 0] + bias[n + 0];
                float v1 = acc[mt][nt][half * 2 + 1] + bias[n + 1];
                if (ACT) { v0 = gelu_exact(v0); v1 = gelu_exact(v1); }
                if (F32OUT) {
                    *(float2*)(Cf + orow * (size_t)N + n) = make_float2(v0, v1);
                } else {
                    *(uint32_t*)(Ch + orow * (size_t)N + n) = pack_hi2(v0, v1);
                }
            }
        }
    }
}

// ---------------- launch -----------------------------------------------------
// __device__ globals passed as kernel args MUST be resolved through
// cudaGetSymbolAddress (host shadow vs device copy under ATS on GB300).
#define SYMADDR(T, var, sym) \
    T* var; { void* _p; cudaGetSymbolAddress(&_p, sym); var = (T*)_p; }

extern "C" void kernel_launch(void* const* d_in, const int* in_sizes, int n_in,
                              void* d_out, int out_size)
{
    const float* x   = (const float*)d_in[0];
    const float* Wr1 = (const float*)d_in[1];
    const float* br1 = (const float*)d_in[2];
    const float* Wr2 = (const float*)d_in[3];
    const float* br2 = (const float*)d_in[4];
    const float* W1  = (const float*)d_in[5];
    const float* b1  = (const float*)d_in[6];
    const float* W2  = (const float*)d_in[7];
    const float* b2  = (const float*)d_in[8];
    const float* Wo  = (const float*)d_in[9];
    const float* bo  = (const float*)d_in[10];

    SYMADDR(fp16,  xhi, g_xhi);  SYMADDR(fp16, xlo, g_xlo);
    SYMADDR(float, Hr,  g_Hr);
    SYMADDR(fp16,  H2,  g_H2);   SYMADDR(fp16, sel, g_sel);

    float* out = (float*)d_out;
    float* out_main   = out;
    float* out_idx    = nullptr;
    float* out_logits = nullptr;
    const long long need_all = (long long)B_TOK * DM + B_TOK + (long long)B_TOK * N_TILES;
    if ((long long)out_size >= need_all) {
        out_idx    = out + (size_t)B_TOK * DM;
        out_logits = out + (size_t)B_TOK * DM + B_TOK;
    } else if ((long long)out_size >= (long long)B_TOK * DM + B_TOK) {
        out_idx = out + (size_t)B_TOK * DM;
    }

    // 1) counters + activation split (fp16 hi/lo)
    zero_kernel<<<1, 32>>>();
    split_acts_kernel<<<(B_TOK * DM / 4) / 256, 256>>>(x, xhi, xlo);

    // 2) router hidden: Hr = gelu(x @ Wr1 + br1)  (fp16 x3 — near-exact)
    hgemm_kernel<0, 3, true, true><<<dim3(DM / 128, B_TOK / 128), 256>>>(
        xhi, xlo, Wr1, br1, Hr, nullptr, DM, DM, B_TOK);

    // 3) logits + argmax + counts; 4) offsets + scatter
    router_argmax_kernel<<<B_TOK / 8, 256>>>(Hr, Wr2, br2, out_logits, out_idx);
    offsets_kernel<<<1, 1>>>();
    scatter_kernel<<<B_TOK / 256, 256>>>();

    // 5) tile MLP layer 1: gather x rows, gelu, fp16 out (compact order), 2-term
    hgemm_kernel<1, 2, true, false><<<dim3(DH / 128, B_TOK / 128, N_TILES), 256>>>(
        xhi, nullptr, W1, b1, nullptr, H2, DH, DM, 0);

    // 6) tile MLP layer 2: compact in, scatter out, fp16 out, 2-term
    hgemm_kernel<2, 2, false, false><<<dim3(DM / 128, B_TOK / 128, N_TILES), 256>>>(
        H2, nullptr, W2, b2, nullptr, sel, DM, DH, 0);

    // 7) output projection (fp32 out to d_out), 2-term
    hgemm_kernel<0, 2, false, true><<<dim3(DM / 128, B_TOK / 128), 256>>>(
        sel, nullptr, Wo, bo, out_main, nullptr, DM, DM, B_TOK);
}

// round 12
// speedup vs baseline: 1.7773x; 1.0217x over previous
#include <cuda_runtime.h>
#include <cuda_fp16.h>
#include <math.h>
#include <stdint.h>

#define B_TOK   4096
#define DM      1024
#define DH      2048
#define N_TILES 8

typedef __half fp16;

// ---------------- scratch (device globals; no allocation allowed) -----------
__device__ fp16  g_xhi [B_TOK * DM];
__device__ fp16  g_xlo [B_TOK * DM];
__device__ float g_Hr  [B_TOK * DM];
__device__ fp16  g_H2  [B_TOK * DH];
__device__ fp16  g_sel [B_TOK * DM];
__device__ int   g_tile[B_TOK];
__device__ int   g_perm[B_TOK];
__device__ int   g_cnt[N_TILES];
__device__ int   g_off[N_TILES];
__device__ int   g_cur[N_TILES];

// ---------------- helpers ----------------------------------------------------
__device__ __forceinline__ uint32_t smem_u32(const void* p) {
    uint32_t a;
    asm("{ .reg .u64 t; cvta.to.shared.u64 t, %1; cvt.u32.u64 %0, t; }"
        : "=r"(a) : "l"(p));
    return a;
}
__device__ __forceinline__ void cp_async16(uint32_t dst, const void* src) {
    asm volatile("cp.async.cg.shared.global [%0], [%1], 16;"
                 :: "r"(dst), "l"(src) : "memory");
}
__device__ __forceinline__ void cp_commit() {
    asm volatile("cp.async.commit_group;" ::: "memory");
}
__device__ __forceinline__ void cp_wait1() {
    asm volatile("cp.async.wait_group 1;" ::: "memory");
}
__device__ __forceinline__ void ldsm_x4(uint32_t* r, uint32_t addr) {
    asm volatile("ldmatrix.sync.aligned.m8n8.x4.shared.b16 {%0,%1,%2,%3}, [%4];"
                 : "=r"(r[0]), "=r"(r[1]), "=r"(r[2]), "=r"(r[3]) : "r"(addr));
}
__device__ __forceinline__ void ldsm_x4_t(uint32_t* r, uint32_t addr) {
    asm volatile("ldmatrix.sync.aligned.m8n8.x4.trans.shared.b16 {%0,%1,%2,%3}, [%4];"
                 : "=r"(r[0]), "=r"(r[1]), "=r"(r[2]), "=r"(r[3]) : "r"(addr));
}
__device__ __forceinline__ void mma16816(float* c, const uint32_t* a, const uint32_t* b) {
    asm volatile("mma.sync.aligned.m16n8k16.row.col.f32.f16.f16.f32 "
                 "{%0,%1,%2,%3}, {%4,%5,%6,%7}, {%8,%9}, {%0,%1,%2,%3};"
                 : "+f"(c[0]), "+f"(c[1]), "+f"(c[2]), "+f"(c[3])
                 : "r"(a[0]), "r"(a[1]), "r"(a[2]), "r"(a[3]),
                   "r"(b[0]), "r"(b[1]));
}
__device__ __forceinline__ float gelu_exact(float v) {
    return 0.5f * v * (1.0f + erff(v * 0.70710678118654752440f));
}
__device__ __forceinline__ uint32_t pack_hi2(float a, float b) {
    __half2 p(__float2half_rn(a), __float2half_rn(b));
    return *(uint32_t*)&p;
}
__device__ __forceinline__ uint32_t pack_lo2(float a, float b, uint32_t hi) {
    __half2 h = *(__half2*)&hi;
    __half2 p(__float2half_rn(a - __half2float(h.x)),
              __float2half_rn(b - __half2float(h.y)));
    return *(uint32_t*)&p;
}

// ---------------- small kernels ---------------------------------------------
__global__ void zero_kernel() {
    int i = threadIdx.x;
    if (i < N_TILES) { g_cnt[i] = 0; g_cur[i] = 0; }
}

__global__ void split_acts_kernel(const float* __restrict__ src,
                                  fp16* __restrict__ xhi, fp16* __restrict__ xlo) {
    int i = blockIdx.x * blockDim.x + threadIdx.x;   // float4 index
    const float4 v = ((const float4*)src)[i];
    uint32_t h0 = pack_hi2(v.x, v.y), h1 = pack_hi2(v.z, v.w);
    uint32_t l0 = pack_lo2(v.x, v.y, h0), l1 = pack_lo2(v.z, v.w, h1);
    ((uint2*)xhi)[i] = make_uint2(h0, h1);
    ((uint2*)xlo)[i] = make_uint2(l0, l1);
}

// ---------------- router logits + argmax ------------------------------------
__global__ __launch_bounds__(256) void router_argmax_kernel(
    const float* __restrict__ Hr, const float* __restrict__ Wr2,
    const float* __restrict__ br2,
    float* __restrict__ out_logits, float* __restrict__ out_idx)
{
    const int token = blockIdx.x * 8 + (threadIdx.x >> 5);
    const int lane  = threadIdx.x & 31;
    const float* h  = Hr + (size_t)token * DM;

    float acc[N_TILES];
#pragma unroll
    for (int n = 0; n < N_TILES; n++) acc[n] = 0.f;
    for (int k = lane; k < DM; k += 32) {
        float hv = h[k];
        float4 w0 = *(const float4*)(Wr2 + (size_t)k * N_TILES);
        float4 w1 = *(const float4*)(Wr2 + (size_t)k * N_TILES + 4);
        acc[0] = fmaf(hv, w0.x, acc[0]); acc[1] = fmaf(hv, w0.y, acc[1]);
        acc[2] = fmaf(hv, w0.z, acc[2]); acc[3] = fmaf(hv, w0.w, acc[3]);
        acc[4] = fmaf(hv, w1.x, acc[4]); acc[5] = fmaf(hv, w1.y, acc[5]);
        acc[6] = fmaf(hv, w1.z, acc[6]); acc[7] = fmaf(hv, w1.w, acc[7]);
    }
#pragma unroll
    for (int n = 0; n < N_TILES; n++)
#pragma unroll
        for (int s = 16; s > 0; s >>= 1)
            acc[n] += __shfl_xor_sync(0xFFFFFFFFu, acc[n], s);
    if (lane == 0) {
        float best = -1e30f; int bi = 0;
#pragma unroll
        for (int n = 0; n < N_TILES; n++) {
            float l = (acc[n] + br2[n]) * 2.0f;
            if (out_logits) out_logits[(size_t)token * N_TILES + n] = l;
            if (l > best) { best = l; bi = n; }
        }
        g_tile[token] = bi;
        atomicAdd(&g_cnt[bi], 1);
        if (out_idx) out_idx[token] = (float)bi;
    }
}

__global__ void offsets_kernel() {
    if (threadIdx.x == 0) {
        int s = 0;
        for (int t = 0; t < N_TILES; t++) { g_off[t] = s; s += g_cnt[t]; }
    }
}

__global__ void scatter_kernel() {
    int i = blockIdx.x * blockDim.x + threadIdx.x;
    if (i < B_TOK) {
        int t = g_tile[i];
        int pos = g_off[t] + atomicAdd(&g_cur[t], 1);
        g_perm[pos] = i;
    }
}

// ---------------- HMMA fp16-split GEMM, fused fp32-weight conversion ---------
// C[M,N] = act(A[M,K] @ W[K,N] + b).
// W: fp32 [K][N] direct; loader converts to hi/lo fp16 in-register, STS
// K-major tiles, B fragments via ldmatrix.x4.trans.
// NTERM==3 (router): D = Ah*Bh + Ah*Bl + Al*Bh  (error ~2^-22; 1 CTA/SM).
// NTERM==2 (big GEMMs): D = Ah*(Bh+Bl) = Ah*W exact-in-W; A lo omitted
//   (~2^-11 rel). 32 MMA/iter; ~120 regs -> 2 CTAs/SM via launch bounds,
//   so one CTA's HMMA stream covers the other's barrier/LDSM bubbles.
// Block 128x128, 256 threads, 8 warps (2Mx4N), warp tile 64x32, BK=16.
// 3 stages x 16KB = 48KB static smem (2 CTAs -> 96KB/SM, fits).

#define BK       16
#define AROWB    32                     // A row bytes (BK fp16)
#define BROWB    256                    // B row bytes (128 fp16)
#define SOFF_AHI 0
#define SOFF_ALO 4096
#define SOFF_BHI 8192
#define SOFF_BLO 12288
#define STAGE_B  16384
#define NSTAGE   3

template<int MODE, int NTERM, bool ACT, bool F32OUT>
__global__ void __launch_bounds__(256, (NTERM == 2) ? 2 : 1) hgemm_kernel(
    const fp16* __restrict__ Ahi, const fp16* __restrict__ Alo,
    const float* __restrict__ Wf,
    const float* __restrict__ bg,
    float* __restrict__ Cf, fp16* __restrict__ Ch,
    int N, int K, int M0)
{
    const int tile = (MODE == 0) ? 0 : blockIdx.z;
    int Mvalid, moff;
    if (MODE == 0) { Mvalid = M0;          moff = 0; }
    else           { Mvalid = g_cnt[tile]; moff = g_off[tile]; }

    const int mstart = blockIdx.y * 128;
    if (mstart >= Mvalid) return;
    const int nstart = blockIdx.x * 128;

    __shared__ __align__(128) char smem[NSTAGE * STAGE_B];
    const uint32_t sb = smem_u32(smem);
    const int tid  = threadIdx.x;
    const int wid  = tid >> 5;
    const int lane = tid & 31;
    const int warp_m = (wid & 1) * 64;
    const int warp_n = (wid >> 1) * 32;
    const int g     = lane >> 2;
    const int tig   = lane & 3;
    const int matid = lane >> 3;
    const int mrow8 = lane & 7;

    // ---- A loader (cp.async): one row per thread-pair, 16B chunk tid&1 ----
    const int lrow = tid >> 1;
    const int kc   = tid & 1;
    const int keo  = kc * 8;
    int mg = mstart + lrow; if (mg > Mvalid - 1) mg = Mvalid - 1;
    size_t aidx;
    if (MODE == 0)      aidx = (size_t)mg;
    else if (MODE == 1) aidx = (size_t)g_perm[moff + mg];
    else                aidx = (size_t)(moff + mg);
    const fp16* gah = Ahi + aidx * (size_t)K;
    const fp16* gal = (NTERM == 3) ? (Alo + aidx * (size_t)K) : nullptr;
    const uint32_t astoff = (uint32_t)lrow * AROWB + (uint32_t)kc * 16;

    // ---- B loader (LDG fp32 + cvt + STS): row tid>>4, 8-float seg tid&15 ----
    const int brow = tid >> 4;
    const int bseg = tid & 15;
    const float* gbf = Wf + (size_t)tile * (size_t)K * (size_t)N
                          + (size_t)nstart + (size_t)bseg * 8;
    const uint32_t bstoff = (uint32_t)brow * BROWB
                          + (uint32_t)(((bseg >> 1) ^ (brow & 7)) * 32)
                          + (uint32_t)((bseg & 1) * 16);

    // ---- ldmatrix addresses ----
    const uint32_t a_ls = (uint32_t)(warp_m + (matid & 1) * 8 + mrow8) * AROWB
                        + (uint32_t)(matid >> 1) * 16;
    const uint32_t bt_row = (uint32_t)((matid & 1) * 8 + mrow8) * BROWB
                          + (uint32_t)(matid >> 1) * 16;
    const uint32_t bt_c0 = (uint32_t)((((warp_n >> 4) + 0) ^ mrow8) * 32);
    const uint32_t bt_c1 = (uint32_t)((((warp_n >> 4) + 1) ^ mrow8) * 32);

    const int nk = K / BK;

    float4 bf0, bf1;   // fp32 B register stage

    // ---- prologue ----
#pragma unroll
    for (int s = 0; s < 2; s++) {
        const uint32_t buf = sb + s * STAGE_B;
        cp_async16(buf + SOFF_AHI + astoff, gah + s * BK + keo);
        if (NTERM == 3)
            cp_async16(buf + SOFF_ALO + astoff, gal + s * BK + keo);
        cp_commit();
    }
    {
        const float* p = gbf + (size_t)brow * N;
        bf0 = *(const float4*)(p);
        bf1 = *(const float4*)(p + 4);
        uint32_t h0 = pack_hi2(bf0.x, bf0.y), h1 = pack_hi2(bf0.z, bf0.w);
        uint32_t h2 = pack_hi2(bf1.x, bf1.y), h3 = pack_hi2(bf1.z, bf1.w);
        uint32_t l0 = pack_lo2(bf0.x, bf0.y, h0), l1 = pack_lo2(bf0.z, bf0.w, h1);
        uint32_t l2 = pack_lo2(bf1.x, bf1.y, h2), l3 = pack_lo2(bf1.z, bf1.w, h3);
        *(uint4*)(smem + SOFF_BHI + bstoff) = make_uint4(h0, h1, h2, h3);
        *(uint4*)(smem + SOFF_BLO + bstoff) = make_uint4(l0, l1, l2, l3);
        if (nk > 1) {
            const float* q = gbf + (size_t)(BK + brow) * N;
            bf0 = *(const float4*)(q);
            bf1 = *(const float4*)(q + 4);
        }
    }

    float acc[4][4][4];
#pragma unroll
    for (int i = 0; i < 4; i++)
#pragma unroll
        for (int j = 0; j < 4; j++)
#pragma unroll
            for (int c = 0; c < 4; c++) acc[i][j][c] = 0.f;

    int sc = 0;   // stage of kt
    int sp = 2;   // stage of kt+2
    for (int kt = 0; kt < nk; kt++) {
        cp_wait1();
        __syncthreads();

        // A(kt+2) via cp.async into stage sp
        if (kt + 2 < nk) {
            const uint32_t buf = sb + sp * STAGE_B;
            const int k0 = (kt + 2) * BK;
            cp_async16(buf + SOFF_AHI + astoff, gah + k0 + keo);
            if (NTERM == 3)
                cp_async16(buf + SOFF_ALO + astoff, gal + k0 + keo);
        }
        cp_commit();

        // B(kt+1): convert regs -> STS into stage (kt+1)%3
        if (kt + 1 < nk) {
            char* buf = smem + ((sc + 1) % NSTAGE) * STAGE_B;
            uint32_t h0 = pack_hi2(bf0.x, bf0.y), h1 = pack_hi2(bf0.z, bf0.w);
            uint32_t h2 = pack_hi2(bf1.x, bf1.y), h3 = pack_hi2(bf1.z, bf1.w);
            uint32_t l0 = pack_lo2(bf0.x, bf0.y, h0), l1 = pack_lo2(bf0.z, bf0.w, h1);
            uint32_t l2 = pack_lo2(bf1.x, bf1.y, h2), l3 = pack_lo2(bf1.z, bf1.w, h3);
            *(uint4*)(buf + SOFF_BHI + bstoff) = make_uint4(h0, h1, h2, h3);
            *(uint4*)(buf + SOFF_BLO + bstoff) = make_uint4(l0, l1, l2, l3);
        }
        // B(kt+2) -> regs
        if (kt + 2 < nk) {
            const float* q = gbf + (size_t)((kt + 2) * BK + brow) * N;
            bf0 = *(const float4*)(q);
            bf1 = *(const float4*)(q + 4);
        }

        const uint32_t st = sb + sc * STAGE_B;

        // B fragments via ldmatrix.trans
        uint32_t Bh[8], Bl[8];
        ldsm_x4_t(&Bh[0], st + SOFF_BHI + bt_row + bt_c0);
        ldsm_x4_t(&Bh[4], st + SOFF_BHI + bt_row + bt_c1);
        ldsm_x4_t(&Bl[0], st + SOFF_BLO + bt_row + bt_c0);
        ldsm_x4_t(&Bl[4], st + SOFF_BLO + bt_row + bt_c1);

#pragma unroll
        for (int mt = 0; mt < 4; mt++) {
            const uint32_t aa = st + a_ls + (uint32_t)mt * 16 * AROWB;
            uint32_t Ah[4], Al[4];
            ldsm_x4(Ah, aa + SOFF_AHI);
            if (NTERM == 3) ldsm_x4(Al, aa + SOFF_ALO);
#pragma unroll
            for (int nt = 0; nt < 4; nt++) {
                const uint32_t* bh = &Bh[(nt >> 1) * 4 + (nt & 1) * 2];
                const uint32_t* bl = &Bl[(nt >> 1) * 4 + (nt & 1) * 2];
                mma16816(acc[mt][nt], Ah, bh);
                mma16816(acc[mt][nt], Ah, bl);
                if (NTERM == 3) mma16816(acc[mt][nt], Al, bh);
            }
        }

        sc = (sc == NSTAGE - 1) ? 0 : sc + 1;
        sp = (sp == NSTAGE - 1) ? 0 : sp + 1;
    }

    // ---- epilogue ----
    const float* bias = bg + (size_t)tile * N;
#pragma unroll
    for (int mt = 0; mt < 4; mt++) {
#pragma unroll
        for (int half = 0; half < 2; half++) {
            const int m = mstart + warp_m + mt * 16 + g + half * 8;
            if (m >= Mvalid) continue;
            size_t orow;
            if (MODE == 0)      orow = (size_t)m;
            else if (MODE == 1) orow = (size_t)(moff + m);
            else                orow = (size_t)g_perm[moff + m];
#pragma unroll
            for (int nt = 0; nt < 4; nt++) {
                const int n = nstart + warp_n + nt * 8 + tig * 2;
                float v0 = acc[mt][nt][half * 2 + 0] + bias[n + 0];
                float v1 = acc[mt][nt][half * 2 + 1] + bias[n + 1];
                if (ACT) { v0 = gelu_exact(v0); v1 = gelu_exact(v1); }
                if (F32OUT) {
                    *(float2*)(Cf + orow * (size_t)N + n) = make_float2(v0, v1);
                } else {
                    *(uint32_t*)(Ch + orow * (size_t)N + n) = pack_hi2(v0, v1);
                }
            }
        }
    }
}

// ---------------- launch -----------------------------------------------------
// __device__ globals passed as kernel args MUST be resolved through
// cudaGetSymbolAddress (host shadow vs device copy under ATS on GB300).
#define SYMADDR(T, var, sym) \
    T* var; { void* _p; cudaGetSymbolAddress(&_p, sym); var = (T*)_p; }

extern "C" void kernel_launch(void* const* d_in, const int* in_sizes, int n_in,
                              void* d_out, int out_size)
{
    const float* x   = (const float*)d_in[0];
    const float* Wr1 = (const float*)d_in[1];
    const float* br1 = (const float*)d_in[2];
    const float* Wr2 = (const float*)d_in[3];
    const float* br2 = (const float*)d_in[4];
    const float* W1  = (const float*)d_in[5];
    const float* b1  = (const float*)d_in[6];
    const float* W2  = (const float*)d_in[7];
    const float* b2  = (const float*)d_in[8];
    const float* Wo  = (const float*)d_in[9];
    const float* bo  = (const float*)d_in[10];

    SYMADDR(fp16,  xhi, g_xhi);  SYMADDR(fp16, xlo, g_xlo);
    SYMADDR(float, Hr,  g_Hr);
    SYMADDR(fp16,  H2,  g_H2);   SYMADDR(fp16, sel, g_sel);

    float* out = (float*)d_out;
    float* out_main   = out;
    float* out_idx    = nullptr;
    float* out_logits = nullptr;
    const long long need_all = (long long)B_TOK * DM + B_TOK + (long long)B_TOK * N_TILES;
    if ((long long)out_size >= need_all) {
        out_idx    = out + (size_t)B_TOK * DM;
        out_logits = out + (size_t)B_TOK * DM + B_TOK;
    } else if ((long long)out_size >= (long long)B_TOK * DM + B_TOK) {
        out_idx = out + (size_t)B_TOK * DM;
    }

    // 1) counters + activation split (fp16 hi/lo)
    zero_kernel<<<1, 32>>>();
    split_acts_kernel<<<(B_TOK * DM / 4) / 256, 256>>>(x, xhi, xlo);

    // 2) router hidden: Hr = gelu(x @ Wr1 + br1)  (fp16 x3 — near-exact)
    hgemm_kernel<0, 3, true, true><<<dim3(DM / 128, B_TOK / 128), 256>>>(
        xhi, xlo, Wr1, br1, Hr, nullptr, DM, DM, B_TOK);

    // 3) logits + argmax + counts; 4) offsets + scatter
    router_argmax_kernel<<<B_TOK / 8, 256>>>(Hr, Wr2, br2, out_logits, out_idx);
    offsets_kernel<<<1, 1>>>();
    scatter_kernel<<<B_TOK / 256, 256>>>();

    // 5) tile MLP layer 1: gather x rows, gelu, fp16 out (compact order), 2-term
    hgemm_kernel<1, 2, true, false><<<dim3(DH / 128, B_TOK / 128, N_TILES), 256>>>(
        xhi, nullptr, W1, b1, nullptr, H2, DH, DM, 0);

    // 6) tile MLP layer 2: compact in, scatter out, fp16 out, 2-term
    hgemm_kernel<2, 2, false, false><<<dim3(DM / 128, B_TOK / 128, N_TILES), 256>>>(
        H2, nullptr, W2, b2, nullptr, sel, DM, DH, 0);

    // 7) output projection (fp32 out to d_out), 2-term
    hgemm_kernel<0, 2, false, true><<<dim3(DM / 128, B_TOK / 128), 256>>>(
        sel, nullptr, Wo, bo, out_main, nullptr, DM, DM, B_TOK);
}

// round 13
// speedup vs baseline: 2.0239x; 1.1388x over previous
#include <cuda_runtime.h>
#include <cuda_fp16.h>
#include <math.h>
#include <stdint.h>

#define B_TOK   4096
#define DM      1024
#define DH      2048
#define N_TILES 8

typedef __half fp16;

// ---------------- scratch (device globals; no allocation allowed) -----------
__device__ fp16  g_xhi [B_TOK * DM];
__device__ fp16  g_xlo [B_TOK * DM];
__device__ float g_Hr  [B_TOK * DM];
__device__ fp16  g_H2  [B_TOK * DH];
__device__ fp16  g_sel [B_TOK * DM];
__device__ int   g_tile[B_TOK];
__device__ int   g_perm[B_TOK];
__device__ int   g_cnt[N_TILES];
__device__ int   g_off[N_TILES];
__device__ int   g_cur[N_TILES];

// ---------------- helpers ----------------------------------------------------
__device__ __forceinline__ uint32_t smem_u32(const void* p) {
    uint32_t a;
    asm("{ .reg .u64 t; cvta.to.shared.u64 t, %1; cvt.u32.u64 %0, t; }"
        : "=r"(a) : "l"(p));
    return a;
}
__device__ __forceinline__ void cp_async16(uint32_t dst, const void* src) {
    asm volatile("cp.async.cg.shared.global [%0], [%1], 16;"
                 :: "r"(dst), "l"(src) : "memory");
}
__device__ __forceinline__ void cp_commit() {
    asm volatile("cp.async.commit_group;" ::: "memory");
}
__device__ __forceinline__ void cp_wait1() {
    asm volatile("cp.async.wait_group 1;" ::: "memory");
}
__device__ __forceinline__ void ldsm_x4(uint32_t* r, uint32_t addr) {
    asm volatile("ldmatrix.sync.aligned.m8n8.x4.shared.b16 {%0,%1,%2,%3}, [%4];"
                 : "=r"(r[0]), "=r"(r[1]), "=r"(r[2]), "=r"(r[3]) : "r"(addr));
}
__device__ __forceinline__ void ldsm_x4_t(uint32_t* r, uint32_t addr) {
    asm volatile("ldmatrix.sync.aligned.m8n8.x4.trans.shared.b16 {%0,%1,%2,%3}, [%4];"
                 : "=r"(r[0]), "=r"(r[1]), "=r"(r[2]), "=r"(r[3]) : "r"(addr));
}
__device__ __forceinline__ void mma16816(float* c, const uint32_t* a, const uint32_t* b) {
    asm volatile("mma.sync.aligned.m16n8k16.row.col.f32.f16.f16.f32 "
                 "{%0,%1,%2,%3}, {%4,%5,%6,%7}, {%8,%9}, {%0,%1,%2,%3};"
                 : "+f"(c[0]), "+f"(c[1]), "+f"(c[2]), "+f"(c[3])
                 : "r"(a[0]), "r"(a[1]), "r"(a[2]), "r"(a[3]),
                   "r"(b[0]), "r"(b[1]));
}
__device__ __forceinline__ float gelu_exact(float v) {
    return 0.5f * v * (1.0f + erff(v * 0.70710678118654752440f));
}
__device__ __forceinline__ uint32_t pack_hi2(float a, float b) {
    __half2 p(__float2half_rn(a), __float2half_rn(b));
    return *(uint32_t*)&p;
}
__device__ __forceinline__ uint32_t pack_lo2(float a, float b, uint32_t hi) {
    __half2 h = *(__half2*)&hi;
    __half2 p(__float2half_rn(a - __half2float(h.x)),
              __float2half_rn(b - __half2float(h.y)));
    return *(uint32_t*)&p;
}

// ---------------- small kernels ---------------------------------------------
__global__ void zero_kernel() {
    int i = threadIdx.x;
    if (i < N_TILES) { g_cnt[i] = 0; g_cur[i] = 0; }
}

__global__ void split_acts_kernel(const float* __restrict__ src,
                                  fp16* __restrict__ xhi, fp16* __restrict__ xlo) {
    int i = blockIdx.x * blockDim.x + threadIdx.x;   // float4 index
    const float4 v = ((const float4*)src)[i];
    uint32_t h0 = pack_hi2(v.x, v.y), h1 = pack_hi2(v.z, v.w);
    uint32_t l0 = pack_lo2(v.x, v.y, h0), l1 = pack_lo2(v.z, v.w, h1);
    ((uint2*)xhi)[i] = make_uint2(h0, h1);
    ((uint2*)xlo)[i] = make_uint2(l0, l1);
}

// ---------------- router logits + argmax ------------------------------------
__global__ __launch_bounds__(256) void router_argmax_kernel(
    const float* __restrict__ Hr, const float* __restrict__ Wr2,
    const float* __restrict__ br2,
    float* __restrict__ out_logits, float* __restrict__ out_idx)
{
    const int token = blockIdx.x * 8 + (threadIdx.x >> 5);
    const int lane  = threadIdx.x & 31;
    const float* h  = Hr + (size_t)token * DM;

    float acc[N_TILES];
#pragma unroll
    for (int n = 0; n < N_TILES; n++) acc[n] = 0.f;
    for (int k = lane; k < DM; k += 32) {
        float hv = h[k];
        float4 w0 = *(const float4*)(Wr2 + (size_t)k * N_TILES);
        float4 w1 = *(const float4*)(Wr2 + (size_t)k * N_TILES + 4);
        acc[0] = fmaf(hv, w0.x, acc[0]); acc[1] = fmaf(hv, w0.y, acc[1]);
        acc[2] = fmaf(hv, w0.z, acc[2]); acc[3] = fmaf(hv, w0.w, acc[3]);
        acc[4] = fmaf(hv, w1.x, acc[4]); acc[5] = fmaf(hv, w1.y, acc[5]);
        acc[6] = fmaf(hv, w1.z, acc[6]); acc[7] = fmaf(hv, w1.w, acc[7]);
    }
#pragma unroll
    for (int n = 0; n < N_TILES; n++)
#pragma unroll
        for (int s = 16; s > 0; s >>= 1)
            acc[n] += __shfl_xor_sync(0xFFFFFFFFu, acc[n], s);
    if (lane == 0) {
        float best = -1e30f; int bi = 0;
#pragma unroll
        for (int n = 0; n < N_TILES; n++) {
            float l = (acc[n] + br2[n]) * 2.0f;
            if (out_logits) out_logits[(size_t)token * N_TILES + n] = l;
            if (l > best) { best = l; bi = n; }
        }
        g_tile[token] = bi;
        atomicAdd(&g_cnt[bi], 1);
        if (out_idx) out_idx[token] = (float)bi;
    }
}

__global__ void offsets_kernel() {
    if (threadIdx.x == 0) {
        int s = 0;
        for (int t = 0; t < N_TILES; t++) { g_off[t] = s; s += g_cnt[t]; }
    }
}

__global__ void scatter_kernel() {
    int i = blockIdx.x * blockDim.x + threadIdx.x;
    if (i < B_TOK) {
        int t = g_tile[i];
        int pos = g_off[t] + atomicAdd(&g_cur[t], 1);
        g_perm[pos] = i;
    }
}

// ---------------- HMMA fp16 GEMM, fused fp32-weight conversion ---------------
// C[M,N] = act(A[M,K] @ W[K,N] + b).
// W: fp32 [K][N] direct; loader converts to fp16 in-register, STS K-major,
// B fragments via ldmatrix.x4.trans.
// NTERM==3 (router): W split hi/lo; D = Ah*Bh + Ah*Bl + Al*Bh (err ~2^-22;
//   protects the argmax; 1 CTA/SM).
// NTERM==1 (big GEMMs): D = Ah*fp16(W). A-lo omitted (~2^-11) and W rounded
//   (~2.8e-4 rms) -> total output err ~6e-4 < 1e-3. 16 MMA/iter; ~110 regs
//   -> 2 CTAs/SM via launch bounds.
// Block 128x128, 256 threads, 8 warps (2Mx4N), warp tile 64x32, BK=16.
// 3 stages x 16KB = 48KB static smem (2 CTAs -> 96KB/SM, fits).

#define BK       16
#define AROWB    32                     // A row bytes (BK fp16)
#define BROWB    256                    // B row bytes (128 fp16)
#define SOFF_AHI 0
#define SOFF_ALO 4096
#define SOFF_BHI 8192
#define SOFF_BLO 12288
#define STAGE_B  16384
#define NSTAGE   3

template<int MODE, int NTERM, bool ACT, bool F32OUT>
__global__ void __launch_bounds__(256, (NTERM == 1) ? 2 : 1) hgemm_kernel(
    const fp16* __restrict__ Ahi, const fp16* __restrict__ Alo,
    const float* __restrict__ Wf,
    const float* __restrict__ bg,
    float* __restrict__ Cf, fp16* __restrict__ Ch,
    int N, int K, int M0)
{
    const int tile = (MODE == 0) ? 0 : blockIdx.z;
    int Mvalid, moff;
    if (MODE == 0) { Mvalid = M0;          moff = 0; }
    else           { Mvalid = g_cnt[tile]; moff = g_off[tile]; }

    const int mstart = blockIdx.y * 128;
    if (mstart >= Mvalid) return;
    const int nstart = blockIdx.x * 128;

    __shared__ __align__(128) char smem[NSTAGE * STAGE_B];
    const uint32_t sb = smem_u32(smem);
    const int tid  = threadIdx.x;
    const int wid  = tid >> 5;
    const int lane = tid & 31;
    const int warp_m = (wid & 1) * 64;
    const int warp_n = (wid >> 1) * 32;
    const int g     = lane >> 2;
    const int tig   = lane & 3;
    const int matid = lane >> 3;
    const int mrow8 = lane & 7;

    // ---- A loader (cp.async): one row per thread-pair, 16B chunk tid&1 ----
    const int lrow = tid >> 1;
    const int kc   = tid & 1;
    const int keo  = kc * 8;
    int mg = mstart + lrow; if (mg > Mvalid - 1) mg = Mvalid - 1;
    size_t aidx;
    if (MODE == 0)      aidx = (size_t)mg;
    else if (MODE == 1) aidx = (size_t)g_perm[moff + mg];
    else                aidx = (size_t)(moff + mg);
    const fp16* gah = Ahi + aidx * (size_t)K;
    const fp16* gal = (NTERM == 3) ? (Alo + aidx * (size_t)K) : nullptr;
    const uint32_t astoff = (uint32_t)lrow * AROWB + (uint32_t)kc * 16;

    // ---- B loader (LDG fp32 + cvt + STS): row tid>>4, 8-float seg tid&15 ----
    const int brow = tid >> 4;
    const int bseg = tid & 15;
    const float* gbf = Wf + (size_t)tile * (size_t)K * (size_t)N
                          + (size_t)nstart + (size_t)bseg * 8;
    const uint32_t bstoff = (uint32_t)brow * BROWB
                          + (uint32_t)(((bseg >> 1) ^ (brow & 7)) * 32)
                          + (uint32_t)((bseg & 1) * 16);

    // ---- ldmatrix addresses ----
    const uint32_t a_ls = (uint32_t)(warp_m + (matid & 1) * 8 + mrow8) * AROWB
                        + (uint32_t)(matid >> 1) * 16;
    const uint32_t bt_row = (uint32_t)((matid & 1) * 8 + mrow8) * BROWB
                          + (uint32_t)(matid >> 1) * 16;
    const uint32_t bt_c0 = (uint32_t)((((warp_n >> 4) + 0) ^ mrow8) * 32);
    const uint32_t bt_c1 = (uint32_t)((((warp_n >> 4) + 1) ^ mrow8) * 32);

    const int nk = K / BK;

    float4 bf0, bf1;   // fp32 B register stage

    // B convert+store helper
    auto stsB = [&](char* buf) {
        uint32_t h0 = pack_hi2(bf0.x, bf0.y), h1 = pack_hi2(bf0.z, bf0.w);
        uint32_t h2 = pack_hi2(bf1.x, bf1.y), h3 = pack_hi2(bf1.z, bf1.w);
        *(uint4*)(buf + SOFF_BHI + bstoff) = make_uint4(h0, h1, h2, h3);
        if (NTERM == 3) {
            uint32_t l0 = pack_lo2(bf0.x, bf0.y, h0), l1 = pack_lo2(bf0.z, bf0.w, h1);
            uint32_t l2 = pack_lo2(bf1.x, bf1.y, h2), l3 = pack_lo2(bf1.z, bf1.w, h3);
            *(uint4*)(buf + SOFF_BLO + bstoff) = make_uint4(l0, l1, l2, l3);
        }
    };

    // ---- prologue ----
#pragma unroll
    for (int s = 0; s < 2; s++) {
        const uint32_t buf = sb + s * STAGE_B;
        cp_async16(buf + SOFF_AHI + astoff, gah + s * BK + keo);
        if (NTERM == 3)
            cp_async16(buf + SOFF_ALO + astoff, gal + s * BK + keo);
        cp_commit();
    }
    {
        const float* p = gbf + (size_t)brow * N;
        bf0 = *(const float4*)(p);
        bf1 = *(const float4*)(p + 4);
        stsB(smem);
        if (nk > 1) {
            const float* q = gbf + (size_t)(BK + brow) * N;
            bf0 = *(const float4*)(q);
            bf1 = *(const float4*)(q + 4);
        }
    }

    float acc[4][4][4];
#pragma unroll
    for (int i = 0; i < 4; i++)
#pragma unroll
        for (int j = 0; j < 4; j++)
#pragma unroll
            for (int c = 0; c < 4; c++) acc[i][j][c] = 0.f;

    int sc = 0;   // stage of kt
    int sp = 2;   // stage of kt+2
    for (int kt = 0; kt < nk; kt++) {
        cp_wait1();
        __syncthreads();

        // A(kt+2) via cp.async into stage sp
        if (kt + 2 < nk) {
            const uint32_t buf = sb + sp * STAGE_B;
            const int k0 = (kt + 2) * BK;
            cp_async16(buf + SOFF_AHI + astoff, gah + k0 + keo);
            if (NTERM == 3)
                cp_async16(buf + SOFF_ALO + astoff, gal + k0 + keo);
        }
        cp_commit();

        // B(kt+1): convert regs -> STS into stage (kt+1)%3
        if (kt + 1 < nk)
            stsB(smem + ((sc + 1) % NSTAGE) * STAGE_B);
        // B(kt+2) -> regs
        if (kt + 2 < nk) {
            const float* q = gbf + (size_t)((kt + 2) * BK + brow) * N;
            bf0 = *(const float4*)(q);
            bf1 = *(const float4*)(q + 4);
        }

        const uint32_t st = sb + sc * STAGE_B;

        // B fragments via ldmatrix.trans
        uint32_t Bh[8], Bl[8];
        ldsm_x4_t(&Bh[0], st + SOFF_BHI + bt_row + bt_c0);
        ldsm_x4_t(&Bh[4], st + SOFF_BHI + bt_row + bt_c1);
        if (NTERM == 3) {
            ldsm_x4_t(&Bl[0], st + SOFF_BLO + bt_row + bt_c0);
            ldsm_x4_t(&Bl[4], st + SOFF_BLO + bt_row + bt_c1);
        }

#pragma unroll
        for (int mt = 0; mt < 4; mt++) {
            const uint32_t aa = st + a_ls + (uint32_t)mt * 16 * AROWB;
            uint32_t Ah[4], Al[4];
            ldsm_x4(Ah, aa + SOFF_AHI);
            if (NTERM == 3) ldsm_x4(Al, aa + SOFF_ALO);
#pragma unroll
            for (int nt = 0; nt < 4; nt++) {
                const uint32_t* bh = &Bh[(nt >> 1) * 4 + (nt & 1) * 2];
                mma16816(acc[mt][nt], Ah, bh);
                if (NTERM == 3) {
                    const uint32_t* bl = &Bl[(nt >> 1) * 4 + (nt & 1) * 2];
                    mma16816(acc[mt][nt], Ah, bl);
                    mma16816(acc[mt][nt], Al, bh);
                }
            }
        }

        sc = (sc == NSTAGE - 1) ? 0 : sc + 1;
        sp = (sp == NSTAGE - 1) ? 0 : sp + 1;
    }

    // ---- epilogue ----
    const float* bias = bg + (size_t)tile * N;
#pragma unroll
    for (int mt = 0; mt < 4; mt++) {
#pragma unroll
        for (int half = 0; half < 2; half++) {
            const int m = mstart + warp_m + mt * 16 + g + half * 8;
            if (m >= Mvalid) continue;
            size_t orow;
            if (MODE == 0)      orow = (size_t)m;
            else if (MODE == 1) orow = (size_t)(moff + m);
            else                orow = (size_t)g_perm[moff + m];
#pragma unroll
            for (int nt = 0; nt < 4; nt++) {
                const int n = nstart + warp_n + nt * 8 + tig * 2;
                float v0 = acc[mt][nt][half * 2 + 0] + bias[n + 0];
                float v1 = acc[mt][nt][half * 2 + 1] + bias[n + 1];
                if (ACT) { v0 = gelu_exact(v0); v1 = gelu_exact(v1); }
                if (F32OUT) {
                    *(float2*)(Cf + orow * (size_t)N + n) = make_float2(v0, v1);
                } else {
                    *(uint32_t*)(Ch + orow * (size_t)N + n) = pack_hi2(v0, v1);
                }
            }
        }
    }
}

// ---------------- launch -----------------------------------------------------
// __device__ globals passed as kernel args MUST be resolved through
// cudaGetSymbolAddress (host shadow vs device copy under ATS on GB300).
#define SYMADDR(T, var, sym) \
    T* var; { void* _p; cudaGetSymbolAddress(&_p, sym); var = (T*)_p; }

extern "C" void kernel_launch(void* const* d_in, const int* in_sizes, int n_in,
                              void* d_out, int out_size)
{
    const float* x   = (const float*)d_in[0];
    const float* Wr1 = (const float*)d_in[1];
    const float* br1 = (const float*)d_in[2];
    const float* Wr2 = (const float*)d_in[3];
    const float* br2 = (const float*)d_in[4];
    const float* W1  = (const float*)d_in[5];
    const float* b1  = (const float*)d_in[6];
    const float* W2  = (const float*)d_in[7];
    const float* b2  = (const float*)d_in[8];
    const float* Wo  = (const float*)d_in[9];
    const float* bo  = (const float*)d_in[10];

    SYMADDR(fp16,  xhi, g_xhi);  SYMADDR(fp16, xlo, g_xlo);
    SYMADDR(float, Hr,  g_Hr);
    SYMADDR(fp16,  H2,  g_H2);   SYMADDR(fp16, sel, g_sel);

    float* out = (float*)d_out;
    float* out_main   = out;
    float* out_idx    = nullptr;
    float* out_logits = nullptr;
    const long long need_all = (long long)B_TOK * DM + B_TOK + (long long)B_TOK * N_TILES;
    if ((long long)out_size >= need_all) {
        out_idx    = out + (size_t)B_TOK * DM;
        out_logits = out + (size_t)B_TOK * DM + B_TOK;
    } else if ((long long)out_size >= (long long)B_TOK * DM + B_TOK) {
        out_idx = out + (size_t)B_TOK * DM;
    }

    // 1) counters + activation split (fp16 hi/lo)
    zero_kernel<<<1, 32>>>();
    split_acts_kernel<<<(B_TOK * DM / 4) / 256, 256>>>(x, xhi, xlo);

    // 2) router hidden: Hr = gelu(x @ Wr1 + br1)  (fp16 x3 — near-exact)
    hgemm_kernel<0, 3, true, true><<<dim3(DM / 128, B_TOK / 128), 256>>>(
        xhi, xlo, Wr1, br1, Hr, nullptr, DM, DM, B_TOK);

    // 3) logits + argmax + counts; 4) offsets + scatter
    router_argmax_kernel<<<B_TOK / 8, 256>>>(Hr, Wr2, br2, out_logits, out_idx);
    offsets_kernel<<<1, 1>>>();
    scatter_kernel<<<B_TOK / 256, 256>>>();

    // 5) tile MLP layer 1: gather x rows, gelu, fp16 out (compact), 1-term
    hgemm_kernel<1, 1, true, false><<<dim3(DH / 128, B_TOK / 128, N_TILES), 256>>>(
        xhi, nullptr, W1, b1, nullptr, H2, DH, DM, 0);

    // 6) tile MLP layer 2: compact in, scatter out, fp16 out, 1-term
    hgemm_kernel<2, 1, false, false><<<dim3(DM / 128, B_TOK / 128, N_TILES), 256>>>(
        H2, nullptr, W2, b2, nullptr, sel, DM, DH, 0);

    // 7) output projection (fp32 out to d_out), 1-term
    hgemm_kernel<0, 1, false, true><<<dim3(DM / 128, B_TOK / 128), 256>>>(
        sel, nullptr, Wo, bo, out_main, nullptr, DM, DM, B_TOK);
}

// round 14
// speedup vs baseline: 2.0380x; 1.0069x over previous
#include <cuda_runtime.h>
#include <cuda_fp16.h>
#include <math.h>
#include <stdint.h>

#define B_TOK   4096
#define DM      1024
#define DH      2048
#define N_TILES 8

typedef __half fp16;

// ---------------- scratch (device globals; no allocation allowed) -----------
__device__ fp16  g_xhi [B_TOK * DM];
__device__ fp16  g_xlo [B_TOK * DM];
__device__ float g_Hr  [B_TOK * DM];
__device__ fp16  g_H2  [B_TOK * DH];
__device__ fp16  g_sel [B_TOK * DM];
__device__ int   g_tile[B_TOK];
__device__ int   g_perm[B_TOK];
__device__ int   g_cnt[N_TILES];
__device__ int   g_off[N_TILES];
__device__ int   g_cur[N_TILES];

// ---------------- helpers ----------------------------------------------------
__device__ __forceinline__ uint32_t smem_u32(const void* p) {
    uint32_t a;
    asm("{ .reg .u64 t; cvta.to.shared.u64 t, %1; cvt.u32.u64 %0, t; }"
        : "=r"(a) : "l"(p));
    return a;
}
__device__ __forceinline__ void cp_async16(uint32_t dst, const void* src) {
    asm volatile("cp.async.cg.shared.global [%0], [%1], 16;"
                 :: "r"(dst), "l"(src) : "memory");
}
__device__ __forceinline__ void cp_commit() {
    asm volatile("cp.async.commit_group;" ::: "memory");
}
__device__ __forceinline__ void cp_wait1() {
    asm volatile("cp.async.wait_group 1;" ::: "memory");
}
__device__ __forceinline__ void ldsm_x4(uint32_t* r, uint32_t addr) {
    asm volatile("ldmatrix.sync.aligned.m8n8.x4.shared.b16 {%0,%1,%2,%3}, [%4];"
                 : "=r"(r[0]), "=r"(r[1]), "=r"(r[2]), "=r"(r[3]) : "r"(addr));
}
__device__ __forceinline__ void ldsm_x4_t(uint32_t* r, uint32_t addr) {
    asm volatile("ldmatrix.sync.aligned.m8n8.x4.trans.shared.b16 {%0,%1,%2,%3}, [%4];"
                 : "=r"(r[0]), "=r"(r[1]), "=r"(r[2]), "=r"(r[3]) : "r"(addr));
}
__device__ __forceinline__ void mma16816(float* c, const uint32_t* a, const uint32_t* b) {
    asm volatile("mma.sync.aligned.m16n8k16.row.col.f32.f16.f16.f32 "
                 "{%0,%1,%2,%3}, {%4,%5,%6,%7}, {%8,%9}, {%0,%1,%2,%3};"
                 : "+f"(c[0]), "+f"(c[1]), "+f"(c[2]), "+f"(c[3])
                 : "r"(a[0]), "r"(a[1]), "r"(a[2]), "r"(a[3]),
                   "r"(b[0]), "r"(b[1]));
}
__device__ __forceinline__ float gelu_exact(float v) {
    return 0.5f * v * (1.0f + erff(v * 0.70710678118654752440f));
}
__device__ __forceinline__ uint32_t pack_hi2(float a, float b) {
    __half2 p(__float2half_rn(a), __float2half_rn(b));
    return *(uint32_t*)&p;
}
__device__ __forceinline__ uint32_t pack_lo2(float a, float b, uint32_t hi) {
    __half2 h = *(__half2*)&hi;
    __half2 p(__float2half_rn(a - __half2float(h.x)),
              __float2half_rn(b - __half2float(h.y)));
    return *(uint32_t*)&p;
}

// ---------------- small kernels ---------------------------------------------
__global__ void zero_kernel() {
    int i = threadIdx.x;
    if (i < N_TILES) { g_cnt[i] = 0; g_cur[i] = 0; }
}

__global__ void split_acts_kernel(const float* __restrict__ src,
                                  fp16* __restrict__ xhi, fp16* __restrict__ xlo) {
    int i = blockIdx.x * blockDim.x + threadIdx.x;   // float4 index
    const float4 v = ((const float4*)src)[i];
    uint32_t h0 = pack_hi2(v.x, v.y), h1 = pack_hi2(v.z, v.w);
    uint32_t l0 = pack_lo2(v.x, v.y, h0), l1 = pack_lo2(v.z, v.w, h1);
    ((uint2*)xhi)[i] = make_uint2(h0, h1);
    ((uint2*)xlo)[i] = make_uint2(l0, l1);
}

// ---------------- router logits + argmax ------------------------------------
__global__ __launch_bounds__(256) void router_argmax_kernel(
    const float* __restrict__ Hr, const float* __restrict__ Wr2,
    const float* __restrict__ br2,
    float* __restrict__ out_logits, float* __restrict__ out_idx)
{
    const int token = blockIdx.x * 8 + (threadIdx.x >> 5);
    const int lane  = threadIdx.x & 31;
    const float* h  = Hr + (size_t)token * DM;

    float acc[N_TILES];
#pragma unroll
    for (int n = 0; n < N_TILES; n++) acc[n] = 0.f;
    for (int k = lane; k < DM; k += 32) {
        float hv = h[k];
        float4 w0 = *(const float4*)(Wr2 + (size_t)k * N_TILES);
        float4 w1 = *(const float4*)(Wr2 + (size_t)k * N_TILES + 4);
        acc[0] = fmaf(hv, w0.x, acc[0]); acc[1] = fmaf(hv, w0.y, acc[1]);
        acc[2] = fmaf(hv, w0.z, acc[2]); acc[3] = fmaf(hv, w0.w, acc[3]);
        acc[4] = fmaf(hv, w1.x, acc[4]); acc[5] = fmaf(hv, w1.y, acc[5]);
        acc[6] = fmaf(hv, w1.z, acc[6]); acc[7] = fmaf(hv, w1.w, acc[7]);
    }
#pragma unroll
    for (int n = 0; n < N_TILES; n++)
#pragma unroll
        for (int s = 16; s > 0; s >>= 1)
            acc[n] += __shfl_xor_sync(0xFFFFFFFFu, acc[n], s);
    if (lane == 0) {
        float best = -1e30f; int bi = 0;
#pragma unroll
        for (int n = 0; n < N_TILES; n++) {
            float l = (acc[n] + br2[n]) * 2.0f;
            if (out_logits) out_logits[(size_t)token * N_TILES + n] = l;
            if (l > best) { best = l; bi = n; }
        }
        g_tile[token] = bi;
        atomicAdd(&g_cnt[bi], 1);
        if (out_idx) out_idx[token] = (float)bi;
    }
}

__global__ void offsets_kernel() {
    if (threadIdx.x == 0) {
        int s = 0;
        for (int t = 0; t < N_TILES; t++) { g_off[t] = s; s += g_cnt[t]; }
    }
}

__global__ void scatter_kernel() {
    int i = blockIdx.x * blockDim.x + threadIdx.x;
    if (i < B_TOK) {
        int t = g_tile[i];
        int pos = g_off[t] + atomicAdd(&g_cur[t], 1);
        g_perm[pos] = i;
    }
}

// ---------------- HMMA fp16 GEMM, fused fp32-weight conversion ---------------
// C[M,N] = act(A[M,K] @ W[K,N] + b).
// NTERM==3 (router): BK=16, W split hi/lo, D = Ah*Bh + Ah*Bl + Al*Bh
//   (err ~2^-22; protects the argmax; 1 CTA/SM). Proven R8 path, unchanged.
// NTERM==1 (big GEMMs): BK=32, D = Ah*fp16(W) — 32 MMA/iter, HALF the
//   iterations of BK=16, amortizing the per-iter barrier/cp.wait/STS costs.
//   A rows 64B, swizzle chunk^((row>>1)&3) -> conflict-free A LDSM.
//   B rows 256B, 32 k-rows, swizzle chunk32^(krow&7) (krow&7 == mrow8 in
//   the trans-LDSM lane map, same as BK=16). 2 CTAs/SM via launch bounds.
// Block 128x128, 256 threads, 8 warps (2Mx4N). 3 x 16KB = 48KB static smem
// in both variants (NTERM1: A 8KB + B 8KB; NTERM3: Ahi/Alo/Bhi/Blo 4KB each).

#define SOFF_ALO 4096
#define SOFF_BHI 8192
#define SOFF_BLO 12288
#define STAGE_B  16384
#define NSTAGE   3

template<int MODE, int NTERM, bool ACT, bool F32OUT>
__global__ void __launch_bounds__(256, (NTERM == 1) ? 2 : 1) hgemm_kernel(
    const fp16* __restrict__ Ahi, const fp16* __restrict__ Alo,
    const float* __restrict__ Wf,
    const float* __restrict__ bg,
    float* __restrict__ Cf, fp16* __restrict__ Ch,
    int N, int K, int M0)
{
    constexpr int BKT  = (NTERM == 1) ? 32 : 16;   // k per stage
    constexpr int AROW = BKT * 2;                  // A row bytes

    const int tile = (MODE == 0) ? 0 : blockIdx.z;
    int Mvalid, moff;
    if (MODE == 0) { Mvalid = M0;          moff = 0; }
    else           { Mvalid = g_cnt[tile]; moff = g_off[tile]; }

    const int mstart = blockIdx.y * 128;
    if (mstart >= Mvalid) return;
    const int nstart = blockIdx.x * 128;

    __shared__ __align__(128) char smem[NSTAGE * STAGE_B];
    const uint32_t sb = smem_u32(smem);
    const int tid  = threadIdx.x;
    const int wid  = tid >> 5;
    const int lane = tid & 31;
    const int warp_m = (wid & 1) * 64;
    const int warp_n = (wid >> 1) * 32;
    const int g     = lane >> 2;
    const int tig   = lane & 3;
    const int matid = lane >> 3;
    const int mrow8 = lane & 7;

    // ---- A loader (cp.async) ----
    const int lrow = tid >> 1;
    int mg = mstart + lrow; if (mg > Mvalid - 1) mg = Mvalid - 1;
    size_t aidx;
    if (MODE == 0)      aidx = (size_t)mg;
    else if (MODE == 1) aidx = (size_t)g_perm[moff + mg];
    else                aidx = (size_t)(moff + mg);
    const fp16* gah = Ahi + aidx * (size_t)K;
    const fp16* gal = (NTERM == 3) ? (Alo + aidx * (size_t)K) : nullptr;
    // NTERM3: one 16B chunk (kc), NTERM1: two chunks kc0,kc0+1 with swizzle
    const int kc   = tid & 1;            // NTERM3 chunk
    const int keo  = kc * 8;
    const uint32_t astoff3 = (uint32_t)lrow * 32 + (uint32_t)kc * 16;
    const int kc0  = (tid & 1) * 2;      // NTERM1 first chunk
    const int aswz_st = (lrow >> 1) & 3;
    const uint32_t ast1_0 = (uint32_t)lrow * 64 + (uint32_t)((kc0      ^ aswz_st) * 16);
    const uint32_t ast1_1 = (uint32_t)lrow * 64 + (uint32_t)(((kc0 + 1) ^ aswz_st) * 16);
    const int ke1_0 = kc0 * 8, ke1_1 = ke1_0 + 8;

    // ---- B loader (LDG fp32 + cvt + STS) ----
    // NTERM3: brow=tid>>4 (16 rows), seg=tid&15 (8 floats)
    // NTERM1: brow=tid>>3 (32 rows), seg=tid&7 (16 floats)
    const int brow3 = tid >> 4, bseg3 = tid & 15;
    const int brow1 = tid >> 3, bseg1 = tid & 7;
    const int browX = (NTERM == 1) ? brow1 : brow3;
    const float* gbf = Wf + (size_t)tile * (size_t)K * (size_t)N
                          + (size_t)nstart
                          + (size_t)((NTERM == 1) ? bseg1 * 16 : bseg3 * 8);
    const uint32_t bstoff = (NTERM == 1)
        ? ((uint32_t)brow1 * 256 + (uint32_t)((bseg1 ^ (brow1 & 7)) * 32))
        : ((uint32_t)brow3 * 256 + (uint32_t)(((bseg3 >> 1) ^ (brow3 & 7)) * 32)
                                  + (uint32_t)((bseg3 & 1) * 16));

    // ---- ldmatrix addresses ----
    // A: NTERM3 constant offset; NTERM1 row-dependent swizzle (mt-invariant)
    const uint32_t a_ls3 = (uint32_t)(warp_m + (matid & 1) * 8 + mrow8) * 32
                         + (uint32_t)(matid >> 1) * 16;
    const int arow_base = warp_m + (matid & 1) * 8 + mrow8;   // + mt*16
    const uint32_t a_base1 = (uint32_t)arow_base * 64;
    const int aswz_ld = (arow_base >> 1) & 3;
    const int matid2 = matid >> 1;
    // B trans (row&7 == mrow8 in both variants)
    const uint32_t bt_row = (uint32_t)((matid & 1) * 8 + mrow8) * 256
                          + (uint32_t)(matid >> 1) * 16;
    const uint32_t bt_c0 = (uint32_t)((((warp_n >> 4) + 0) ^ mrow8) * 32);
    const uint32_t bt_c1 = (uint32_t)((((warp_n >> 4) + 1) ^ mrow8) * 32);

    const int nk = K / BKT;

    float4 bf[4];   // fp32 B register stage (NTERM1 uses all 4, NTERM3 uses 2)

    auto ldgB = [&](int kt) {
        const float* q = gbf + (size_t)(kt * BKT + browX) * N;
        bf[0] = *(const float4*)(q);
        bf[1] = *(const float4*)(q + 4);
        if (NTERM == 1) {
            bf[2] = *(const float4*)(q + 8);
            bf[3] = *(const float4*)(q + 12);
        }
    };
    auto stsB = [&](char* buf) {
        uint32_t h0 = pack_hi2(bf[0].x, bf[0].y), h1 = pack_hi2(bf[0].z, bf[0].w);
        uint32_t h2 = pack_hi2(bf[1].x, bf[1].y), h3 = pack_hi2(bf[1].z, bf[1].w);
        *(uint4*)(buf + SOFF_BHI + bstoff) = make_uint4(h0, h1, h2, h3);
        if (NTERM == 1) {
            uint32_t h4 = pack_hi2(bf[2].x, bf[2].y), h5 = pack_hi2(bf[2].z, bf[2].w);
            uint32_t h6 = pack_hi2(bf[3].x, bf[3].y), h7 = pack_hi2(bf[3].z, bf[3].w);
            *(uint4*)(buf + SOFF_BHI + bstoff + 16) = make_uint4(h4, h5, h6, h7);
        }
        if (NTERM == 3) {
            uint32_t l0 = pack_lo2(bf[0].x, bf[0].y, h0), l1 = pack_lo2(bf[0].z, bf[0].w, h1);
            uint32_t l2 = pack_lo2(bf[1].x, bf[1].y, h2), l3 = pack_lo2(bf[1].z, bf[1].w, h3);
            *(uint4*)(buf + SOFF_BLO + bstoff) = make_uint4(l0, l1, l2, l3);
        }
    };
    auto cpA = [&](int kt, uint32_t buf) {
        const int k0 = kt * BKT;
        if (NTERM == 1) {
            cp_async16(buf + ast1_0, gah + k0 + ke1_0);
            cp_async16(buf + ast1_1, gah + k0 + ke1_1);
        } else {
            cp_async16(buf + astoff3, gah + k0 + keo);
            cp_async16(buf + SOFF_ALO + astoff3, gal + k0 + keo);
        }
    };

    // ---- prologue ----
    cpA(0, sb);              cp_commit();
    cpA(1, sb + STAGE_B);    cp_commit();
    ldgB(0); stsB(smem);
    if (nk > 1) ldgB(1);

    float acc[4][4][4];
#pragma unroll
    for (int i = 0; i < 4; i++)
#pragma unroll
        for (int j = 0; j < 4; j++)
#pragma unroll
            for (int c = 0; c < 4; c++) acc[i][j][c] = 0.f;

    int sc = 0;   // stage of kt
    int sp = 2;   // stage of kt+2
    for (int kt = 0; kt < nk; kt++) {
        cp_wait1();
        __syncthreads();

        if (kt + 2 < nk) cpA(kt + 2, sb + sp * STAGE_B);
        cp_commit();

        if (kt + 1 < nk) stsB(smem + ((sc + 1) % NSTAGE) * STAGE_B);
        if (kt + 2 < nk) ldgB(kt + 2);

        const uint32_t st = sb + sc * STAGE_B;

        if (NTERM == 3) {
            uint32_t Bh[8], Bl[8];
            ldsm_x4_t(&Bh[0], st + SOFF_BHI + bt_row + bt_c0);
            ldsm_x4_t(&Bh[4], st + SOFF_BHI + bt_row + bt_c1);
            ldsm_x4_t(&Bl[0], st + SOFF_BLO + bt_row + bt_c0);
            ldsm_x4_t(&Bl[4], st + SOFF_BLO + bt_row + bt_c1);
#pragma unroll
            for (int mt = 0; mt < 4; mt++) {
                const uint32_t aa = st + a_ls3 + (uint32_t)mt * 16 * 32;
                uint32_t Ah[4], Al[4];
                ldsm_x4(Ah, aa);
                ldsm_x4(Al, aa + SOFF_ALO);
#pragma unroll
                for (int nt = 0; nt < 4; nt++) {
                    const uint32_t* bh = &Bh[(nt >> 1) * 4 + (nt & 1) * 2];
                    const uint32_t* bl = &Bl[(nt >> 1) * 4 + (nt & 1) * 2];
                    mma16816(acc[mt][nt], Ah, bh);
                    mma16816(acc[mt][nt], Ah, bl);
                    mma16816(acc[mt][nt], Al, bh);
                }
            }
        } else {
#pragma unroll
            for (int ks = 0; ks < 2; ks++) {
                uint32_t Bh[8];
                const uint32_t bb = st + SOFF_BHI + bt_row + (uint32_t)ks * 16 * 256;
                ldsm_x4_t(&Bh[0], bb + bt_c0);
                ldsm_x4_t(&Bh[4], bb + bt_c1);
                const int kchunk = ks * 2 + matid2;
                const uint32_t ak = (uint32_t)((kchunk ^ aswz_ld) * 16);
#pragma unroll
                for (int mt = 0; mt < 4; mt++) {
                    uint32_t Ah[4];
                    ldsm_x4(Ah, st + a_base1 + (uint32_t)mt * 1024 + ak);
#pragma unroll
                    for (int nt = 0; nt < 4; nt++)
                        mma16816(acc[mt][nt], Ah, &Bh[(nt >> 1) * 4 + (nt & 1) * 2]);
                }
            }
        }

        sc = (sc == NSTAGE - 1) ? 0 : sc + 1;
        sp = (sp == NSTAGE - 1) ? 0 : sp + 1;
    }

    // ---- epilogue ----
    const float* bias = bg + (size_t)tile * N;
#pragma unroll
    for (int mt = 0; mt < 4; mt++) {
#pragma unroll
        for (int half = 0; half < 2; half++) {
            const int m = mstart + warp_m + mt * 16 + g + half * 8;
            if (m >= Mvalid) continue;
            size_t orow;
            if (MODE == 0)      orow = (size_t)m;
            else if (MODE == 1) orow = (size_t)(moff + m);
            else                orow = (size_t)g_perm[moff + m];
#pragma unroll
            for (int nt = 0; nt < 4; nt++) {
                const int n = nstart + warp_n + nt * 8 + tig * 2;
                float v0 = acc[mt][nt][half * 2 + 0] + bias[n + 0];
                float v1 = acc[mt][nt][half * 2 + 1] + bias[n + 1];
                if (ACT) { v0 = gelu_exact(v0); v1 = gelu_exact(v1); }
                if (F32OUT) {
                    *(float2*)(Cf + orow * (size_t)N + n) = make_float2(v0, v1);
                } else {
                    *(uint32_t*)(Ch + orow * (size_t)N + n) = pack_hi2(v0, v1);
                }
            }
        }
    }
}

// ---------------- launch -----------------------------------------------------
// __device__ globals passed as kernel args MUST be resolved through
// cudaGetSymbolAddress (host shadow vs device copy under ATS on GB300).
#define SYMADDR(T, var, sym) \
    T* var; { void* _p; cudaGetSymbolAddress(&_p, sym); var = (T*)_p; }

extern "C" void kernel_launch(void* const* d_in, const int* in_sizes, int n_in,
                              void* d_out, int out_size)
{
    const float* x   = (const float*)d_in[0];
    const float* Wr1 = (const float*)d_in[1];
    const float* br1 = (const float*)d_in[2];
    const float* Wr2 = (const float*)d_in[3];
    const float* br2 = (const float*)d_in[4];
    const float* W1  = (const float*)d_in[5];
    const float* b1  = (const float*)d_in[6];
    const float* W2  = (const float*)d_in[7];
    const float* b2  = (const float*)d_in[8];
    const float* Wo  = (const float*)d_in[9];
    const float* bo  = (const float*)d_in[10];

    SYMADDR(fp16,  xhi, g_xhi);  SYMADDR(fp16, xlo, g_xlo);
    SYMADDR(float, Hr,  g_Hr);
    SYMADDR(fp16,  H2,  g_H2);   SYMADDR(fp16, sel, g_sel);

    float* out = (float*)d_out;
    float* out_main   = out;
    float* out_idx    = nullptr;
    float* out_logits = nullptr;
    const long long need_all = (long long)B_TOK * DM + B_TOK + (long long)B_TOK * N_TILES;
    if ((long long)out_size >= need_all) {
        out_idx    = out + (size_t)B_TOK * DM;
        out_logits = out + (size_t)B_TOK * DM + B_TOK;
    } else if ((long long)out_size >= (long long)B_TOK * DM + B_TOK) {
        out_idx = out + (size_t)B_TOK * DM;
    }

    // 1) counters + activation split (fp16 hi/lo)
    zero_kernel<<<1, 32>>>();
    split_acts_kernel<<<(B_TOK * DM / 4) / 256, 256>>>(x, xhi, xlo);

    // 2) router hidden: Hr = gelu(x @ Wr1 + br1)  (fp16 x3, BK=16 — near-exact)
    hgemm_kernel<0, 3, true, true><<<dim3(DM / 128, B_TOK / 128), 256>>>(
        xhi, xlo, Wr1, br1, Hr, nullptr, DM, DM, B_TOK);

    // 3) logits + argmax + counts; 4) offsets + scatter
    router_argmax_kernel<<<B_TOK / 8, 256>>>(Hr, Wr2, br2, out_logits, out_idx);
    offsets_kernel<<<1, 1>>>();
    scatter_kernel<<<B_TOK / 256, 256>>>();

    // 5) tile MLP layer 1: gather x rows, gelu, fp16 out (compact), 1-term BK=32
    hgemm_kernel<1, 1, true, false><<<dim3(DH / 128, B_TOK / 128, N_TILES), 256>>>(
        xhi, nullptr, W1, b1, nullptr, H2, DH, DM, 0);

    // 6) tile MLP layer 2: compact in, scatter out, fp16 out, 1-term BK=32
    hgemm_kernel<2, 1, false, false><<<dim3(DM / 128, B_TOK / 128, N_TILES), 256>>>(
        H2, nullptr, W2, b2, nullptr, sel, DM, DH, 0);

    // 7) output projection (fp32 out to d_out), 1-term BK=32
    hgemm_kernel<0, 1, false, true><<<dim3(DM / 128, B_TOK / 128), 256>>>(
        sel, nullptr, Wo, bo, out_main, nullptr, DM, DM, B_TOK);
}

// round 15
// speedup vs baseline: 2.0545x; 1.0081x over previous
#include <cuda_runtime.h>
#include <cuda_fp16.h>
#include <math.h>
#include <stdint.h>

#define B_TOK   4096
#define DM      1024
#define DH      2048
#define N_TILES 8

typedef __half fp16;

// ---------------- scratch (device globals; no allocation allowed) -----------
__device__ fp16  g_xhi [B_TOK * DM];
__device__ fp16  g_xlo [B_TOK * DM];
__device__ float g_Hr  [B_TOK * DM];
__device__ fp16  g_H2  [B_TOK * DH];
__device__ fp16  g_sel [B_TOK * DM];
__device__ int   g_tile[B_TOK];
__device__ int   g_perm[B_TOK];
__device__ int   g_cnt[N_TILES];
__device__ int   g_off[N_TILES];
__device__ int   g_cur[N_TILES];

// ---------------- helpers ----------------------------------------------------
__device__ __forceinline__ uint32_t smem_u32(const void* p) {
    uint32_t a;
    asm("{ .reg .u64 t; cvta.to.shared.u64 t, %1; cvt.u32.u64 %0, t; }"
        : "=r"(a) : "l"(p));
    return a;
}
__device__ __forceinline__ void cp_async16(uint32_t dst, const void* src) {
    asm volatile("cp.async.cg.shared.global [%0], [%1], 16;"
                 :: "r"(dst), "l"(src) : "memory");
}
__device__ __forceinline__ void cp_commit() {
    asm volatile("cp.async.commit_group;" ::: "memory");
}
__device__ __forceinline__ void cp_wait1() {
    asm volatile("cp.async.wait_group 1;" ::: "memory");
}
__device__ __forceinline__ void ldsm_x4(uint32_t* r, uint32_t addr) {
    asm volatile("ldmatrix.sync.aligned.m8n8.x4.shared.b16 {%0,%1,%2,%3}, [%4];"
                 : "=r"(r[0]), "=r"(r[1]), "=r"(r[2]), "=r"(r[3]) : "r"(addr));
}
__device__ __forceinline__ void ldsm_x4_t(uint32_t* r, uint32_t addr) {
    asm volatile("ldmatrix.sync.aligned.m8n8.x4.trans.shared.b16 {%0,%1,%2,%3}, [%4];"
                 : "=r"(r[0]), "=r"(r[1]), "=r"(r[2]), "=r"(r[3]) : "r"(addr));
}
__device__ __forceinline__ void mma16816(float* c, const uint32_t* a, const uint32_t* b) {
    asm volatile("mma.sync.aligned.m16n8k16.row.col.f32.f16.f16.f32 "
                 "{%0,%1,%2,%3}, {%4,%5,%6,%7}, {%8,%9}, {%0,%1,%2,%3};"
                 : "+f"(c[0]), "+f"(c[1]), "+f"(c[2]), "+f"(c[3])
                 : "r"(a[0]), "r"(a[1]), "r"(a[2]), "r"(a[3]),
                   "r"(b[0]), "r"(b[1]));
}
__device__ __forceinline__ float gelu_exact(float v) {
    return 0.5f * v * (1.0f + erff(v * 0.70710678118654752440f));
}
__device__ __forceinline__ uint32_t pack_hi2(float a, float b) {
    __half2 p(__float2half_rn(a), __float2half_rn(b));
    return *(uint32_t*)&p;
}
__device__ __forceinline__ uint32_t pack_lo2(float a, float b, uint32_t hi) {
    __half2 h = *(__half2*)&hi;
    __half2 p(__float2half_rn(a - __half2float(h.x)),
              __float2half_rn(b - __half2float(h.y)));
    return *(uint32_t*)&p;
}

// ---------------- small kernels ---------------------------------------------
// split_acts also zeroes the per-run counters (block 0) — saves one launch.
__global__ void split_acts_kernel(const float* __restrict__ src,
                                  fp16* __restrict__ xhi, fp16* __restrict__ xlo) {
    if (blockIdx.x == 0 && threadIdx.x < N_TILES) {
        g_cnt[threadIdx.x] = 0;
        g_cur[threadIdx.x] = 0;
    }
    int i = blockIdx.x * blockDim.x + threadIdx.x;   // float4 index
    const float4 v = ((const float4*)src)[i];
    uint32_t h0 = pack_hi2(v.x, v.y), h1 = pack_hi2(v.z, v.w);
    uint32_t l0 = pack_lo2(v.x, v.y, h0), l1 = pack_lo2(v.z, v.w, h1);
    ((uint2*)xhi)[i] = make_uint2(h0, h1);
    ((uint2*)xlo)[i] = make_uint2(l0, l1);
}

// ---------------- router logits + argmax ------------------------------------
__global__ __launch_bounds__(256) void router_argmax_kernel(
    const float* __restrict__ Hr, const float* __restrict__ Wr2,
    const float* __restrict__ br2,
    float* __restrict__ out_logits, float* __restrict__ out_idx)
{
    const int token = blockIdx.x * 8 + (threadIdx.x >> 5);
    const int lane  = threadIdx.x & 31;
    const float* h  = Hr + (size_t)token * DM;

    float acc[N_TILES];
#pragma unroll
    for (int n = 0; n < N_TILES; n++) acc[n] = 0.f;
    for (int k = lane; k < DM; k += 32) {
        float hv = h[k];
        float4 w0 = *(const float4*)(Wr2 + (size_t)k * N_TILES);
        float4 w1 = *(const float4*)(Wr2 + (size_t)k * N_TILES + 4);
        acc[0] = fmaf(hv, w0.x, acc[0]); acc[1] = fmaf(hv, w0.y, acc[1]);
        acc[2] = fmaf(hv, w0.z, acc[2]); acc[3] = fmaf(hv, w0.w, acc[3]);
        acc[4] = fmaf(hv, w1.x, acc[4]); acc[5] = fmaf(hv, w1.y, acc[5]);
        acc[6] = fmaf(hv, w1.z, acc[6]); acc[7] = fmaf(hv, w1.w, acc[7]);
    }
#pragma unroll
    for (int n = 0; n < N_TILES; n++)
#pragma unroll
        for (int s = 16; s > 0; s >>= 1)
            acc[n] += __shfl_xor_sync(0xFFFFFFFFu, acc[n], s);
    if (lane == 0) {
        float best = -1e30f; int bi = 0;
#pragma unroll
        for (int n = 0; n < N_TILES; n++) {
            float l = (acc[n] + br2[n]) * 2.0f;
            if (out_logits) out_logits[(size_t)token * N_TILES + n] = l;
            if (l > best) { best = l; bi = n; }
        }
        g_tile[token] = bi;
        atomicAdd(&g_cnt[bi], 1);
        if (out_idx) out_idx[token] = (float)bi;
    }
}

// scatter also derives offsets from g_cnt (prefix over 8 values) and block 0
// persists g_off for the GEMM kernels — saves the offsets launch.
__global__ void scatter_kernel() {
    int i = blockIdx.x * blockDim.x + threadIdx.x;
    int c0 = g_cnt[0], c1 = g_cnt[1], c2 = g_cnt[2], c3 = g_cnt[3];
    int c4 = g_cnt[4], c5 = g_cnt[5], c6 = g_cnt[6];
    int off[N_TILES];
    off[0] = 0;
    off[1] = c0;            off[2] = off[1] + c1;  off[3] = off[2] + c2;
    off[4] = off[3] + c3;   off[5] = off[4] + c4;  off[6] = off[5] + c5;
    off[7] = off[6] + c6;
    if (blockIdx.x == 0 && threadIdx.x < N_TILES)
        g_off[threadIdx.x] = off[threadIdx.x];
    if (i < B_TOK) {
        int t = g_tile[i];
        int pos = off[t] + atomicAdd(&g_cur[t], 1);
        g_perm[pos] = i;
    }
}

// ---------------- HMMA fp16 GEMM, fused fp32-weight conversion ---------------
// C[M,N] = act(A[M,K] @ W[K,N] + b).
// NTERM==3 (router): BK=16, W split hi/lo, D = Ah*Bh + Ah*Bl + Al*Bh
//   (err ~2^-22; protects the argmax; 1 CTA/SM).
// NTERM==1 (big GEMMs): BK=32, D = Ah*fp16(W); A-lo omitted (~2^-11), W
//   rounded (~2.8e-4 rms). 2 CTAs/SM via launch bounds.
// Block 128x128, 256 threads, 8 warps (2Mx4N). 3 x 16KB = 48KB static smem.

#define SOFF_ALO 4096
#define SOFF_BHI 8192
#define SOFF_BLO 12288
#define STAGE_B  16384
#define NSTAGE   3

template<int MODE, int NTERM, bool ACT, bool F32OUT>
__global__ void __launch_bounds__(256, (NTERM == 1) ? 2 : 1) hgemm_kernel(
    const fp16* __restrict__ Ahi, const fp16* __restrict__ Alo,
    const float* __restrict__ Wf,
    const float* __restrict__ bg,
    float* __restrict__ Cf, fp16* __restrict__ Ch,
    int N, int K, int M0)
{
    constexpr int BKT = (NTERM == 1) ? 32 : 16;   // k per stage

    const int tile = (MODE == 0) ? 0 : blockIdx.z;
    int Mvalid, moff;
    if (MODE == 0) { Mvalid = M0;          moff = 0; }
    else           { Mvalid = g_cnt[tile]; moff = g_off[tile]; }

    const int mstart = blockIdx.y * 128;
    if (mstart >= Mvalid) return;
    const int nstart = blockIdx.x * 128;

    __shared__ __align__(128) char smem[NSTAGE * STAGE_B];
    const uint32_t sb = smem_u32(smem);
    const int tid  = threadIdx.x;
    const int wid  = tid >> 5;
    const int lane = tid & 31;
    const int warp_m = (wid & 1) * 64;
    const int warp_n = (wid >> 1) * 32;
    const int g     = lane >> 2;
    const int tig   = lane & 3;
    const int matid = lane >> 3;
    const int mrow8 = lane & 7;

    // ---- A loader (cp.async) ----
    const int lrow = tid >> 1;
    int mg = mstart + lrow; if (mg > Mvalid - 1) mg = Mvalid - 1;
    size_t aidx;
    if (MODE == 0)      aidx = (size_t)mg;
    else if (MODE == 1) aidx = (size_t)g_perm[moff + mg];
    else                aidx = (size_t)(moff + mg);
    const fp16* gah = Ahi + aidx * (size_t)K;
    const fp16* gal = (NTERM == 3) ? (Alo + aidx * (size_t)K) : nullptr;
    const int kc   = tid & 1;            // NTERM3 chunk
    const int keo  = kc * 8;
    const uint32_t astoff3 = (uint32_t)lrow * 32 + (uint32_t)kc * 16;
    const int kc0  = (tid & 1) * 2;      // NTERM1 first chunk
    const int aswz_st = (lrow >> 1) & 3;
    const uint32_t ast1_0 = (uint32_t)lrow * 64 + (uint32_t)((kc0      ^ aswz_st) * 16);
    const uint32_t ast1_1 = (uint32_t)lrow * 64 + (uint32_t)(((kc0 + 1) ^ aswz_st) * 16);
    const int ke1_0 = kc0 * 8, ke1_1 = ke1_0 + 8;

    // ---- B loader (LDG fp32 + cvt + STS) ----
    const int brow3 = tid >> 4, bseg3 = tid & 15;
    const int brow1 = tid >> 3, bseg1 = tid & 7;
    const int browX = (NTERM == 1) ? brow1 : brow3;
    const float* gbf = Wf + (size_t)tile * (size_t)K * (size_t)N
                          + (size_t)nstart
                          + (size_t)((NTERM == 1) ? bseg1 * 16 : bseg3 * 8);
    const uint32_t bstoff = (NTERM == 1)
        ? ((uint32_t)brow1 * 256 + (uint32_t)((bseg1 ^ (brow1 & 7)) * 32))
        : ((uint32_t)brow3 * 256 + (uint32_t)(((bseg3 >> 1) ^ (brow3 & 7)) * 32)
                                  + (uint32_t)((bseg3 & 1) * 16));

    // ---- ldmatrix addresses ----
    const uint32_t a_ls3 = (uint32_t)(warp_m + (matid & 1) * 8 + mrow8) * 32
                         + (uint32_t)(matid >> 1) * 16;
    const int arow_base = warp_m + (matid & 1) * 8 + mrow8;   // + mt*16
    const uint32_t a_base1 = (uint32_t)arow_base * 64;
    const int aswz_ld = (arow_base >> 1) & 3;
    const int matid2 = matid >> 1;
    const uint32_t bt_row = (uint32_t)((matid & 1) * 8 + mrow8) * 256
                          + (uint32_t)(matid >> 1) * 16;
    const uint32_t bt_c0 = (uint32_t)((((warp_n >> 4) + 0) ^ mrow8) * 32);
    const uint32_t bt_c1 = (uint32_t)((((warp_n >> 4) + 1) ^ mrow8) * 32);

    const int nk = K / BKT;

    float4 bf[4];   // fp32 B register stage (NTERM1 uses all 4, NTERM3 uses 2)

    auto ldgB = [&](int kt) {
        const float* q = gbf + (size_t)(kt * BKT + browX) * N;
        bf[0] = *(const float4*)(q);
        bf[1] = *(const float4*)(q + 4);
        if (NTERM == 1) {
            bf[2] = *(const float4*)(q + 8);
            bf[3] = *(const float4*)(q + 12);
        }
    };
    auto stsB = [&](char* buf) {
        uint32_t h0 = pack_hi2(bf[0].x, bf[0].y), h1 = pack_hi2(bf[0].z, bf[0].w);
        uint32_t h2 = pack_hi2(bf[1].x, bf[1].y), h3 = pack_hi2(bf[1].z, bf[1].w);
        *(uint4*)(buf + SOFF_BHI + bstoff) = make_uint4(h0, h1, h2, h3);
        if (NTERM == 1) {
            uint32_t h4 = pack_hi2(bf[2].x, bf[2].y), h5 = pack_hi2(bf[2].z, bf[2].w);
            uint32_t h6 = pack_hi2(bf[3].x, bf[3].y), h7 = pack_hi2(bf[3].z, bf[3].w);
            *(uint4*)(buf + SOFF_BHI + bstoff + 16) = make_uint4(h4, h5, h6, h7);
        }
        if (NTERM == 3) {
            uint32_t l0 = pack_lo2(bf[0].x, bf[0].y, h0), l1 = pack_lo2(bf[0].z, bf[0].w, h1);
            uint32_t l2 = pack_lo2(bf[1].x, bf[1].y, h2), l3 = pack_lo2(bf[1].z, bf[1].w, h3);
            *(uint4*)(buf + SOFF_BLO + bstoff) = make_uint4(l0, l1, l2, l3);
        }
    };
    auto cpA = [&](int kt, uint32_t buf) {
        const int k0 = kt * BKT;
        if (NTERM == 1) {
            cp_async16(buf + ast1_0, gah + k0 + ke1_0);
            cp_async16(buf + ast1_1, gah + k0 + ke1_1);
        } else {
            cp_async16(buf + astoff3, gah + k0 + keo);
            cp_async16(buf + SOFF_ALO + astoff3, gal + k0 + keo);
        }
    };

    // ---- prologue ----
    cpA(0, sb);              cp_commit();
    cpA(1, sb + STAGE_B);    cp_commit();
    ldgB(0); stsB(smem);
    if (nk > 1) ldgB(1);

    float acc[4][4][4];
#pragma unroll
    for (int i = 0; i < 4; i++)
#pragma unroll
        for (int j = 0; j < 4; j++)
#pragma unroll
            for (int c = 0; c < 4; c++) acc[i][j][c] = 0.f;

    int sc = 0;   // stage of kt
    int sp = 2;   // stage of kt+2
    for (int kt = 0; kt < nk; kt++) {
        cp_wait1();
        __syncthreads();

        if (kt + 2 < nk) cpA(kt + 2, sb + sp * STAGE_B);
        cp_commit();

        if (kt + 1 < nk) stsB(smem + ((sc + 1) % NSTAGE) * STAGE_B);
        if (kt + 2 < nk) ldgB(kt + 2);

        const uint32_t st = sb + sc * STAGE_B;

        if (NTERM == 3) {
            uint32_t Bh[8], Bl[8];
            ldsm_x4_t(&Bh[0], st + SOFF_BHI + bt_row + bt_c0);
            ldsm_x4_t(&Bh[4], st + SOFF_BHI + bt_row + bt_c1);
            ldsm_x4_t(&Bl[0], st + SOFF_BLO + bt_row + bt_c0);
            ldsm_x4_t(&Bl[4], st + SOFF_BLO + bt_row + bt_c1);
#pragma unroll
            for (int mt = 0; mt < 4; mt++) {
                const uint32_t aa = st + a_ls3 + (uint32_t)mt * 16 * 32;
                uint32_t Ah[4], Al[4];
                ldsm_x4(Ah, aa);
                ldsm_x4(Al, aa + SOFF_ALO);
#pragma unroll
                for (int nt = 0; nt < 4; nt++) {
                    const uint32_t* bh = &Bh[(nt >> 1) * 4 + (nt & 1) * 2];
                    const uint32_t* bl = &Bl[(nt >> 1) * 4 + (nt & 1) * 2];
                    mma16816(acc[mt][nt], Ah, bh);
                    mma16816(acc[mt][nt], Ah, bl);
                    mma16816(acc[mt][nt], Al, bh);
                }
            }
        } else {
#pragma unroll
            for (int ks = 0; ks < 2; ks++) {
                uint32_t Bh[8];
                const uint32_t bb = st + SOFF_BHI + bt_row + (uint32_t)ks * 16 * 256;
                ldsm_x4_t(&Bh[0], bb + bt_c0);
                ldsm_x4_t(&Bh[4], bb + bt_c1);
                const int kchunk = ks * 2 + matid2;
                const uint32_t ak = (uint32_t)((kchunk ^ aswz_ld) * 16);
#pragma unroll
                for (int mt = 0; mt < 4; mt++) {
                    uint32_t Ah[4];
                    ldsm_x4(Ah, st + a_base1 + (uint32_t)mt * 1024 + ak);
#pragma unroll
                    for (int nt = 0; nt < 4; nt++)
                        mma16816(acc[mt][nt], Ah, &Bh[(nt >> 1) * 4 + (nt & 1) * 2]);
                }
            }
        }

        sc = (sc == NSTAGE - 1) ? 0 : sc + 1;
        sp = (sp == NSTAGE - 1) ? 0 : sp + 1;
    }

    // ---- epilogue ----
    const float* bias = bg + (size_t)tile * N;
#pragma unroll
    for (int mt = 0; mt < 4; mt++) {
#pragma unroll
        for (int half = 0; half < 2; half++) {
            const int m = mstart + warp_m + mt * 16 + g + half * 8;
            if (m >= Mvalid) continue;
            size_t orow;
            if (MODE == 0)      orow = (size_t)m;
            else if (MODE == 1) orow = (size_t)(moff + m);
            else                orow = (size_t)g_perm[moff + m];
#pragma unroll
            for (int nt = 0; nt < 4; nt++) {
                const int n = nstart + warp_n + nt * 8 + tig * 2;
                float v0 = acc[mt][nt][half * 2 + 0] + bias[n + 0];
                float v1 = acc[mt][nt][half * 2 + 1] + bias[n + 1];
                if (ACT) { v0 = gelu_exact(v0); v1 = gelu_exact(v1); }
                if (F32OUT) {
                    *(float2*)(Cf + orow * (size_t)N + n) = make_float2(v0, v1);
                } else {
                    *(uint32_t*)(Ch + orow * (size_t)N + n) = pack_hi2(v0, v1);
                }
            }
        }
    }
}

// ---------------- launch -----------------------------------------------------
// __device__ globals passed as kernel args MUST be resolved through
// cudaGetSymbolAddress (host shadow vs device copy under ATS on GB300).
#define SYMADDR(T, var, sym) \
    T* var; { void* _p; cudaGetSymbolAddress(&_p, sym); var = (T*)_p; }

extern "C" void kernel_launch(void* const* d_in, const int* in_sizes, int n_in,
                              void* d_out, int out_size)
{
    const float* x   = (const float*)d_in[0];
    const float* Wr1 = (const float*)d_in[1];
    const float* br1 = (const float*)d_in[2];
    const float* Wr2 = (const float*)d_in[3];
    const float* br2 = (const float*)d_in[4];
    const float* W1  = (const float*)d_in[5];
    const float* b1  = (const float*)d_in[6];
    const float* W2  = (const float*)d_in[7];
    const float* b2  = (const float*)d_in[8];
    const float* Wo  = (const float*)d_in[9];
    const float* bo  = (const float*)d_in[10];

    SYMADDR(fp16,  xhi, g_xhi);  SYMADDR(fp16, xlo, g_xlo);
    SYMADDR(float, Hr,  g_Hr);
    SYMADDR(fp16,  H2,  g_H2);   SYMADDR(fp16, sel, g_sel);

    float* out = (float*)d_out;
    float* out_main   = out;
    float* out_idx    = nullptr;
    float* out_logits = nullptr;
    const long long need_all = (long long)B_TOK * DM + B_TOK + (long long)B_TOK * N_TILES;
    if ((long long)out_size >= need_all) {
        out_idx    = out + (size_t)B_TOK * DM;
        out_logits = out + (size_t)B_TOK * DM + B_TOK;
    } else if ((long long)out_size >= (long long)B_TOK * DM + B_TOK) {
        out_idx = out + (size_t)B_TOK * DM;
    }

    // 1) activation split (also zeroes counters)             [launch 1]
    split_acts_kernel<<<(B_TOK * DM / 4) / 256, 256>>>(x, xhi, xlo);

    // 2) router hidden (fp16 x3, BK=16 — near-exact)          [launch 2]
    hgemm_kernel<0, 3, true, true><<<dim3(DM / 128, B_TOK / 128), 256>>>(
        xhi, xlo, Wr1, br1, Hr, nullptr, DM, DM, B_TOK);

    // 3) logits + argmax + counts                             [launch 3]
    router_argmax_kernel<<<B_TOK / 8, 256>>>(Hr, Wr2, br2, out_logits, out_idx);

    // 4) offsets (in-kernel prefix) + scatter                  [launch 4]
    scatter_kernel<<<B_TOK / 256, 256>>>();

    // 5) tile MLP layer 1 (gather, gelu, 1-term BK=32)         [launch 5]
    hgemm_kernel<1, 1, true, false><<<dim3(DH / 128, B_TOK / 128, N_TILES), 256>>>(
        xhi, nullptr, W1, b1, nullptr, H2, DH, DM, 0);

    // 6) tile MLP layer 2 (compact->scatter, 1-term BK=32)     [launch 6: ncu]
    hgemm_kernel<2, 1, false, false><<<dim3(DM / 128, B_TOK / 128, N_TILES), 256>>>(
        H2, nullptr, W2, b2, nullptr, sel, DM, DH, 0);

    // 7) output projection (fp32 out), 1-term BK=32            [launch 7]
    hgemm_kernel<0, 1, false, true><<<dim3(DM / 128, B_TOK / 128), 256>>>(
        sel, nullptr, Wo, bo, out_main, nullptr, DM, DM, B_TOK);
}

// round 16
// speedup vs baseline: 2.3057x; 1.1222x over previous
#include <cuda_runtime.h>
#include <cuda_fp16.h>
#include <math.h>
#include <stdint.h>

#define B_TOK   4096
#define DM      1024
#define DH      2048
#define N_TILES 8

typedef __half fp16;

// ---------------- scratch (device globals; no allocation allowed) -----------
__device__ fp16  g_xhi [B_TOK * DM];
__device__ fp16  g_xlo [B_TOK * DM];
__device__ float g_Hr  [B_TOK * DM];
__device__ fp16  g_H2  [B_TOK * DH];
__device__ fp16  g_sel [B_TOK * DM];
// pre-converted fp16 weights (same [K][N] layout as the fp32 inputs)
__device__ fp16  g_Wr1h[DM * DM], g_Wr1l[DM * DM];
__device__ fp16  g_W1h [N_TILES * DM * DH];
__device__ fp16  g_W2h [N_TILES * DH * DM];
__device__ fp16  g_Woh [DM * DM];
__device__ int   g_tile[B_TOK];
__device__ int   g_perm[B_TOK];
__device__ int   g_cnt[N_TILES];
__device__ int   g_off[N_TILES];
__device__ int   g_cur[N_TILES];

// ---------------- helpers ----------------------------------------------------
__device__ __forceinline__ uint32_t smem_u32(const void* p) {
    uint32_t a;
    asm("{ .reg .u64 t; cvta.to.shared.u64 t, %1; cvt.u32.u64 %0, t; }"
        : "=r"(a) : "l"(p));
    return a;
}
__device__ __forceinline__ void cp_async16(uint32_t dst, const void* src) {
    asm volatile("cp.async.cg.shared.global [%0], [%1], 16;"
                 :: "r"(dst), "l"(src) : "memory");
}
__device__ __forceinline__ void cp_commit() {
    asm volatile("cp.async.commit_group;" ::: "memory");
}
__device__ __forceinline__ void cp_wait1() {
    asm volatile("cp.async.wait_group 1;" ::: "memory");
}
__device__ __forceinline__ void ldsm_x4(uint32_t* r, uint32_t addr) {
    asm volatile("ldmatrix.sync.aligned.m8n8.x4.shared.b16 {%0,%1,%2,%3}, [%4];"
                 : "=r"(r[0]), "=r"(r[1]), "=r"(r[2]), "=r"(r[3]) : "r"(addr));
}
__device__ __forceinline__ void ldsm_x4_t(uint32_t* r, uint32_t addr) {
    asm volatile("ldmatrix.sync.aligned.m8n8.x4.trans.shared.b16 {%0,%1,%2,%3}, [%4];"
                 : "=r"(r[0]), "=r"(r[1]), "=r"(r[2]), "=r"(r[3]) : "r"(addr));
}
__device__ __forceinline__ void mma16816(float* c, const uint32_t* a, const uint32_t* b) {
    asm volatile("mma.sync.aligned.m16n8k16.row.col.f32.f16.f16.f32 "
                 "{%0,%1,%2,%3}, {%4,%5,%6,%7}, {%8,%9}, {%0,%1,%2,%3};"
                 : "+f"(c[0]), "+f"(c[1]), "+f"(c[2]), "+f"(c[3])
                 : "r"(a[0]), "r"(a[1]), "r"(a[2]), "r"(a[3]),
                   "r"(b[0]), "r"(b[1]));
}
__device__ __forceinline__ float gelu_exact(float v) {
    return 0.5f * v * (1.0f + erff(v * 0.70710678118654752440f));
}
__device__ __forceinline__ uint32_t pack_hi2(float a, float b) {
    __half2 p(__float2half_rn(a), __float2half_rn(b));
    return *(uint32_t*)&p;
}
__device__ __forceinline__ uint32_t pack_lo2(float a, float b, uint32_t hi) {
    __half2 h = *(__half2*)&hi;
    __half2 p(__float2half_rn(a - __half2float(h.x)),
              __float2half_rn(b - __half2float(h.y)));
    return *(uint32_t*)&p;
}

// ---------------- small kernels ---------------------------------------------
// split_acts also zeroes the per-run counters (block 0).
__global__ void split_acts_kernel(const float* __restrict__ src,
                                  fp16* __restrict__ xhi, fp16* __restrict__ xlo) {
    if (blockIdx.x == 0 && threadIdx.x < N_TILES) {
        g_cnt[threadIdx.x] = 0;
        g_cur[threadIdx.x] = 0;
    }
    int i = blockIdx.x * blockDim.x + threadIdx.x;   // float4 index
    const float4 v = ((const float4*)src)[i];
    uint32_t h0 = pack_hi2(v.x, v.y), h1 = pack_hi2(v.z, v.w);
    uint32_t l0 = pack_lo2(v.x, v.y, h0), l1 = pack_lo2(v.z, v.w, h1);
    ((uint2*)xhi)[i] = make_uint2(h0, h1);
    ((uint2*)xlo)[i] = make_uint2(l0, l1);
}

// one-time fp32 -> fp16 weight conversion (layout preserved)
template<bool HAS_LO>
__global__ void cvt_weights_kernel(const float* __restrict__ W,
                                   fp16* __restrict__ Wh, fp16* __restrict__ Wl) {
    int i = blockIdx.x * blockDim.x + threadIdx.x;   // float4 index
    const float4 v = ((const float4*)W)[i];
    uint32_t h0 = pack_hi2(v.x, v.y), h1 = pack_hi2(v.z, v.w);
    ((uint2*)Wh)[i] = make_uint2(h0, h1);
    if (HAS_LO) {
        uint32_t l0 = pack_lo2(v.x, v.y, h0), l1 = pack_lo2(v.z, v.w, h1);
        ((uint2*)Wl)[i] = make_uint2(l0, l1);
    }
}

// ---------------- router logits + argmax ------------------------------------
__global__ __launch_bounds__(256) void router_argmax_kernel(
    const float* __restrict__ Hr, const float* __restrict__ Wr2,
    const float* __restrict__ br2,
    float* __restrict__ out_logits, float* __restrict__ out_idx)
{
    const int token = blockIdx.x * 8 + (threadIdx.x >> 5);
    const int lane  = threadIdx.x & 31;
    const float* h  = Hr + (size_t)token * DM;

    float acc[N_TILES];
#pragma unroll
    for (int n = 0; n < N_TILES; n++) acc[n] = 0.f;
    for (int k = lane; k < DM; k += 32) {
        float hv = h[k];
        float4 w0 = *(const float4*)(Wr2 + (size_t)k * N_TILES);
        float4 w1 = *(const float4*)(Wr2 + (size_t)k * N_TILES + 4);
        acc[0] = fmaf(hv, w0.x, acc[0]); acc[1] = fmaf(hv, w0.y, acc[1]);
        acc[2] = fmaf(hv, w0.z, acc[2]); acc[3] = fmaf(hv, w0.w, acc[3]);
        acc[4] = fmaf(hv, w1.x, acc[4]); acc[5] = fmaf(hv, w1.y, acc[5]);
        acc[6] = fmaf(hv, w1.z, acc[6]); acc[7] = fmaf(hv, w1.w, acc[7]);
    }
#pragma unroll
    for (int n = 0; n < N_TILES; n++)
#pragma unroll
        for (int s = 16; s > 0; s >>= 1)
            acc[n] += __shfl_xor_sync(0xFFFFFFFFu, acc[n], s);
    if (lane == 0) {
        float best = -1e30f; int bi = 0;
#pragma unroll
        for (int n = 0; n < N_TILES; n++) {
            float l = (acc[n] + br2[n]) * 2.0f;
            if (out_logits) out_logits[(size_t)token * N_TILES + n] = l;
            if (l > best) { best = l; bi = n; }
        }
        g_tile[token] = bi;
        atomicAdd(&g_cnt[bi], 1);
        if (out_idx) out_idx[token] = (float)bi;
    }
}

// scatter also derives offsets from g_cnt (block 0 persists g_off).
__global__ void scatter_kernel() {
    int i = blockIdx.x * blockDim.x + threadIdx.x;
    int c0 = g_cnt[0], c1 = g_cnt[1], c2 = g_cnt[2], c3 = g_cnt[3];
    int c4 = g_cnt[4], c5 = g_cnt[5], c6 = g_cnt[6];
    int off[N_TILES];
    off[0] = 0;
    off[1] = c0;            off[2] = off[1] + c1;  off[3] = off[2] + c2;
    off[4] = off[3] + c3;   off[5] = off[4] + c4;  off[6] = off[5] + c5;
    off[7] = off[6] + c6;
    if (blockIdx.x == 0 && threadIdx.x < N_TILES)
        g_off[threadIdx.x] = off[threadIdx.x];
    if (i < B_TOK) {
        int t = g_tile[i];
        int pos = off[t] + atomicAdd(&g_cur[t], 1);
        g_perm[pos] = i;
    }
}

// ---------------- HMMA fp16 GEMM, pre-converted fp16 weights -----------------
// C[M,N] = act(A[M,K] @ W[K,N] + b). W given as fp16 [K][N] (hi, and lo for
// NTERM==3). Both A and B tiles arrive via cp.async (no in-loop conversion).
// NTERM==3 (router): BK=16, D = Ah*Bh + Ah*Bl + Al*Bh (err ~2^-22; 1 CTA/SM).
// NTERM==1 (big GEMMs): BK=32, D = Ah*Bh (A-lo ~2^-11 and W rounding ~2.8e-4
//   accepted). 2 CTAs/SM via launch bounds.
// Block 128x128, 256 threads, 8 warps (2Mx4N). 3 x 16KB = 48KB static smem.

#define SOFF_ALO 4096
#define SOFF_BHI 8192
#define SOFF_BLO 12288
#define STAGE_B  16384
#define NSTAGE   3

template<int MODE, int NTERM, bool ACT, bool F32OUT>
__global__ void __launch_bounds__(256, (NTERM == 1) ? 2 : 1) hgemm_kernel(
    const fp16* __restrict__ Ahi, const fp16* __restrict__ Alo,
    const fp16* __restrict__ Wh, const fp16* __restrict__ Wl,
    const float* __restrict__ bg,
    float* __restrict__ Cf, fp16* __restrict__ Ch,
    int N, int K, int M0)
{
    constexpr int BKT = (NTERM == 1) ? 32 : 16;   // k per stage

    const int tile = (MODE == 0) ? 0 : blockIdx.z;
    int Mvalid, moff;
    if (MODE == 0) { Mvalid = M0;          moff = 0; }
    else           { Mvalid = g_cnt[tile]; moff = g_off[tile]; }

    const int mstart = blockIdx.y * 128;
    if (mstart >= Mvalid) return;
    const int nstart = blockIdx.x * 128;

    __shared__ __align__(128) char smem[NSTAGE * STAGE_B];
    const uint32_t sb = smem_u32(smem);
    const int tid  = threadIdx.x;
    const int wid  = tid >> 5;
    const int lane = tid & 31;
    const int warp_m = (wid & 1) * 64;
    const int warp_n = (wid >> 1) * 32;
    const int g     = lane >> 2;
    const int tig   = lane & 3;
    const int matid = lane >> 3;
    const int mrow8 = lane & 7;

    // ---- A loader (cp.async) ----
    const int lrow = tid >> 1;
    int mg = mstart + lrow; if (mg > Mvalid - 1) mg = Mvalid - 1;
    size_t aidx;
    if (MODE == 0)      aidx = (size_t)mg;
    else if (MODE == 1) aidx = (size_t)g_perm[moff + mg];
    else                aidx = (size_t)(moff + mg);
    const fp16* gah = Ahi + aidx * (size_t)K;
    const fp16* gal = (NTERM == 3) ? (Alo + aidx * (size_t)K) : nullptr;
    const int kc   = tid & 1;            // NTERM3 chunk
    const int keo  = kc * 8;
    const uint32_t astoff3 = (uint32_t)lrow * 32 + (uint32_t)kc * 16;
    const int kc0  = (tid & 1) * 2;      // NTERM1 first chunk
    const int aswz_st = (lrow >> 1) & 3;
    const uint32_t ast1_0 = (uint32_t)lrow * 64 + (uint32_t)((kc0      ^ aswz_st) * 16);
    const uint32_t ast1_1 = (uint32_t)lrow * 64 + (uint32_t)(((kc0 + 1) ^ aswz_st) * 16);
    const int ke1_0 = kc0 * 8, ke1_1 = ke1_0 + 8;

    // ---- B loader (cp.async from fp16 weights, swizzled dst) ----
    const fp16* gbh = Wh + (size_t)tile * (size_t)K * (size_t)N + nstart;
    const fp16* gbl = (NTERM == 3)
        ? (Wl + (size_t)tile * (size_t)K * (size_t)N + nstart) : nullptr;
    // NTERM1: 32 rows x 16 chunks; 8 threads/row, 2 chunks each
    const int b1row = tid >> 3;
    const int b1c0  = tid & 7;
    const int b1c1  = b1c0 + 8;
    const uint32_t b1st0 = (uint32_t)b1row * 256
                         + (uint32_t)((((b1c0 >> 1) ^ (b1row & 7)) * 32) + (b1c0 & 1) * 16);
    const uint32_t b1st1 = (uint32_t)b1row * 256
                         + (uint32_t)((((b1c1 >> 1) ^ (b1row & 7)) * 32) + (b1c1 & 1) * 16);
    // NTERM3: 16 rows x 16 chunks; 1 chunk per thread (hi and lo)
    const int b3row = tid >> 4;
    const int b3c   = tid & 15;
    const uint32_t b3st = (uint32_t)b3row * 256
                        + (uint32_t)((((b3c >> 1) ^ (b3row & 7)) * 32) + (b3c & 1) * 16);

    // ---- ldmatrix addresses ----
    const uint32_t a_ls3 = (uint32_t)(warp_m + (matid & 1) * 8 + mrow8) * 32
                         + (uint32_t)(matid >> 1) * 16;
    const int arow_base = warp_m + (matid & 1) * 8 + mrow8;   // + mt*16
    const uint32_t a_base1 = (uint32_t)arow_base * 64;
    const int aswz_ld = (arow_base >> 1) & 3;
    const int matid2 = matid >> 1;
    const uint32_t bt_row = (uint32_t)((matid & 1) * 8 + mrow8) * 256
                          + (uint32_t)(matid >> 1) * 16;
    const uint32_t bt_c0 = (uint32_t)((((warp_n >> 4) + 0) ^ mrow8) * 32);
    const uint32_t bt_c1 = (uint32_t)((((warp_n >> 4) + 1) ^ mrow8) * 32);

    const int nk = K / BKT;

    auto cpStage = [&](int kt, uint32_t buf) {
        const int k0 = kt * BKT;
        if (NTERM == 1) {
            cp_async16(buf + ast1_0, gah + k0 + ke1_0);
            cp_async16(buf + ast1_1, gah + k0 + ke1_1);
            const fp16* br = gbh + (size_t)(k0 + b1row) * N;
            cp_async16(buf + SOFF_BHI + b1st0, br + b1c0 * 8);
            cp_async16(buf + SOFF_BHI + b1st1, br + b1c1 * 8);
        } else {
            cp_async16(buf + astoff3, gah + k0 + keo);
            cp_async16(buf + SOFF_ALO + astoff3, gal + k0 + keo);
            const fp16* brh = gbh + (size_t)(k0 + b3row) * N;
            const fp16* brl = gbl + (size_t)(k0 + b3row) * N;
            cp_async16(buf + SOFF_BHI + b3st, brh + b3c * 8);
            cp_async16(buf + SOFF_BLO + b3st, brl + b3c * 8);
        }
    };

    // ---- prologue ----
    cpStage(0, sb);             cp_commit();
    cpStage(1, sb + STAGE_B);   cp_commit();

    float acc[4][4][4];
#pragma unroll
    for (int i = 0; i < 4; i++)
#pragma unroll
        for (int j = 0; j < 4; j++)
#pragma unroll
            for (int c = 0; c < 4; c++) acc[i][j][c] = 0.f;

    int sc = 0;   // stage of kt
    int sp = 2;   // stage of kt+2
    for (int kt = 0; kt < nk; kt++) {
        cp_wait1();
        __syncthreads();

        if (kt + 2 < nk) cpStage(kt + 2, sb + sp * STAGE_B);
        cp_commit();

        const uint32_t st = sb + sc * STAGE_B;

        if (NTERM == 3) {
            uint32_t Bh[8], Bl[8];
            ldsm_x4_t(&Bh[0], st + SOFF_BHI + bt_row + bt_c0);
            ldsm_x4_t(&Bh[4], st + SOFF_BHI + bt_row + bt_c1);
            ldsm_x4_t(&Bl[0], st + SOFF_BLO + bt_row + bt_c0);
            ldsm_x4_t(&Bl[4], st + SOFF_BLO + bt_row + bt_c1);
#pragma unroll
            for (int mt = 0; mt < 4; mt++) {
                const uint32_t aa = st + a_ls3 + (uint32_t)mt * 16 * 32;
                uint32_t Ah[4], Al[4];
                ldsm_x4(Ah, aa);
                ldsm_x4(Al, aa + SOFF_ALO);
#pragma unroll
                for (int nt = 0; nt < 4; nt++) {
                    const uint32_t* bh = &Bh[(nt >> 1) * 4 + (nt & 1) * 2];
                    const uint32_t* bl = &Bl[(nt >> 1) * 4 + (nt & 1) * 2];
                    mma16816(acc[mt][nt], Ah, bh);
                    mma16816(acc[mt][nt], Ah, bl);
                    mma16816(acc[mt][nt], Al, bh);
                }
            }
        } else {
#pragma unroll
            for (int ks = 0; ks < 2; ks++) {
                uint32_t Bh[8];
                const uint32_t bb = st + SOFF_BHI + bt_row + (uint32_t)ks * 16 * 256;
                ldsm_x4_t(&Bh[0], bb + bt_c0);
                ldsm_x4_t(&Bh[4], bb + bt_c1);
                const int kchunk = ks * 2 + matid2;
                const uint32_t ak = (uint32_t)((kchunk ^ aswz_ld) * 16);
#pragma unroll
                for (int mt = 0; mt < 4; mt++) {
                    uint32_t Ah[4];
                    ldsm_x4(Ah, st + a_base1 + (uint32_t)mt * 1024 + ak);
#pragma unroll
                    for (int nt = 0; nt < 4; nt++)
                        mma16816(acc[mt][nt], Ah, &Bh[(nt >> 1) * 4 + (nt & 1) * 2]);
                }
            }
        }

        sc = (sc == NSTAGE - 1) ? 0 : sc + 1;
        sp = (sp == NSTAGE - 1) ? 0 : sp + 1;
    }

    // ---- epilogue ----
    const float* bias = bg + (size_t)tile * N;
#pragma unroll
    for (int mt = 0; mt < 4; mt++) {
#pragma unroll
        for (int half = 0; half < 2; half++) {
            const int m = mstart + warp_m + mt * 16 + g + half * 8;
            if (m >= Mvalid) continue;
            size_t orow;
            if (MODE == 0)      orow = (size_t)m;
            else if (MODE == 1) orow = (size_t)(moff + m);
            else                orow = (size_t)g_perm[moff + m];
#pragma unroll
            for (int nt = 0; nt < 4; nt++) {
                const int n = nstart + warp_n + nt * 8 + tig * 2;
                float v0 = acc[mt][nt][half * 2 + 0] + bias[n + 0];
                float v1 = acc[mt][nt][half * 2 + 1] + bias[n + 1];
                if (ACT) { v0 = gelu_exact(v0); v1 = gelu_exact(v1); }
                if (F32OUT) {
                    *(float2*)(Cf + orow * (size_t)N + n) = make_float2(v0, v1);
                } else {
                    *(uint32_t*)(Ch + orow * (size_t)N + n) = pack_hi2(v0, v1);
                }
            }
        }
    }
}

// ---------------- launch -----------------------------------------------------
// __device__ globals passed as kernel args MUST be resolved through
// cudaGetSymbolAddress (host shadow vs device copy under ATS on GB300).
#define SYMADDR(T, var, sym) \
    T* var; { void* _p; cudaGetSymbolAddress(&_p, sym); var = (T*)_p; }

extern "C" void kernel_launch(void* const* d_in, const int* in_sizes, int n_in,
                              void* d_out, int out_size)
{
    const float* x   = (const float*)d_in[0];
    const float* Wr1 = (const float*)d_in[1];
    const float* br1 = (const float*)d_in[2];
    const float* Wr2 = (const float*)d_in[3];
    const float* br2 = (const float*)d_in[4];
    const float* W1  = (const float*)d_in[5];
    const float* b1  = (const float*)d_in[6];
    const float* W2  = (const float*)d_in[7];
    const float* b2  = (const float*)d_in[8];
    const float* Wo  = (const float*)d_in[9];
    const float* bo  = (const float*)d_in[10];

    SYMADDR(fp16,  xhi,  g_xhi);   SYMADDR(fp16, xlo,  g_xlo);
    SYMADDR(float, Hr,   g_Hr);
    SYMADDR(fp16,  H2,   g_H2);    SYMADDR(fp16, sel,  g_sel);
    SYMADDR(fp16,  Wr1h, g_Wr1h);  SYMADDR(fp16, Wr1l, g_Wr1l);
    SYMADDR(fp16,  W1h,  g_W1h);
    SYMADDR(fp16,  W2h,  g_W2h);
    SYMADDR(fp16,  Woh,  g_Woh);

    float* out = (float*)d_out;
    float* out_main   = out;
    float* out_idx    = nullptr;
    float* out_logits = nullptr;
    const long long need_all = (long long)B_TOK * DM + B_TOK + (long long)B_TOK * N_TILES;
    if ((long long)out_size >= need_all) {
        out_idx    = out + (size_t)B_TOK * DM;
        out_logits = out + (size_t)B_TOK * DM + B_TOK;
    } else if ((long long)out_size >= (long long)B_TOK * DM + B_TOK) {
        out_idx = out + (size_t)B_TOK * DM;
    }

    // 1) activation split (also zeroes counters)              [launch 1]
    split_acts_kernel<<<(B_TOK * DM / 4) / 256, 256>>>(x, xhi, xlo);

    // 2) one-time weight conversion fp32 -> fp16              [launches 2-5]
    cvt_weights_kernel<true ><<<(DM * DM / 4) / 256, 256>>>(Wr1, Wr1h, Wr1l);
    cvt_weights_kernel<false><<<(N_TILES * DM * DH / 4) / 256, 256>>>(W1, W1h, nullptr);
    cvt_weights_kernel<false><<<(N_TILES * DH * DM / 4) / 256, 256>>>(W2, W2h, nullptr);
    cvt_weights_kernel<false><<<(DM * DM / 4) / 256, 256>>>(Wo, Woh, nullptr);

    // 3) router hidden (fp16 x3, BK=16 — near-exact)          [launch 6: ncu]
    hgemm_kernel<0, 3, true, true><<<dim3(DM / 128, B_TOK / 128), 256>>>(
        xhi, xlo, Wr1h, Wr1l, br1, Hr, nullptr, DM, DM, B_TOK);

    // 4) logits + argmax + counts                             [launch 7]
    router_argmax_kernel<<<B_TOK / 8, 256>>>(Hr, Wr2, br2, out_logits, out_idx);

    // 5) offsets (in-kernel prefix) + scatter                  [launch 8]
    scatter_kernel<<<B_TOK / 256, 256>>>();

    // 6) tile MLP layer 1 (gather, gelu, 1-term BK=32)         [launch 9]
    hgemm_kernel<1, 1, true, false><<<dim3(DH / 128, B_TOK / 128, N_TILES), 256>>>(
        xhi, nullptr, W1h, nullptr, b1, nullptr, H2, DH, DM, 0);

    // 7) tile MLP layer 2 (compact->scatter, 1-term BK=32)     [launch 10]
    hgemm_kernel<2, 1, false, false><<<dim3(DM / 128, B_TOK / 128, N_TILES), 256>>>(
        H2, nullptr, W2h, nullptr, b2, nullptr, sel, DM, DH, 0);

    // 8) output projection (fp32 out), 1-term BK=32            [launch 11]
    hgemm_kernel<0, 1, false, true><<<dim3(DM / 128, B_TOK / 128), 256>>>(
        sel, nullptr, Woh, nullptr, bo, out_main, nullptr, DM, DM, B_TOK);
}